// round 14
// baseline (speedup 1.0000x reference)
#include <cuda_runtime.h>
#include <cuda_bf16.h>
#include <cuda_fp16.h>
#include <cstdint>

// Problem constants
#define BB  2
#define SS  2048
#define DD  1024
#define HH  16
#define DHH 64
#define MM  (BB*SS)    // 4096
#define BHH (BB*HH)    // 32

#define QSCALE (0.125f * 1.44269504088896340736f)   // 1/sqrt(64) * log2(e)

// ---------------------------------------------------------------------------
// Scratch (device globals)
// ---------------------------------------------------------------------------
__device__ float g_attn[(size_t)BB*SS*SS];     // head-0 masked scores (32MB)
__device__ int   g_maskmode;

__device__ __nv_bfloat16 g_key_hi[(size_t)MM*DD],  g_key_lo[(size_t)MM*DD];
__device__ __nv_bfloat16 g_val_hi[(size_t)MM*DD],  g_val_lo[(size_t)MM*DD];
__device__ __nv_bfloat16 g_qry_hi[(size_t)MM*DD],  g_qry_lo[(size_t)MM*DD];
__device__ __nv_bfloat16 g_ctx_hi[(size_t)MM*DD],  g_ctx_lo[(size_t)MM*DD];
__device__ __nv_bfloat16 g_wk_hi[(size_t)DD*DD],   g_wk_lo[(size_t)DD*DD];
__device__ __nv_bfloat16 g_wv_hi[(size_t)DD*DD],   g_wv_lo[(size_t)DD*DD];
__device__ __nv_bfloat16 g_wq_hi[(size_t)DD*DD],   g_wq_lo[(size_t)DD*DD];
__device__ __nv_bfloat16 g_wo_hi[(size_t)DD*DD],   g_wo_lo[(size_t)DD*DD];
__device__ __nv_bfloat16 g_qs_hi[(size_t)BHH*SS*DHH], g_qs_lo[(size_t)BHH*SS*DHH];
__device__ __nv_bfloat16 g_ks_hi[(size_t)BHH*SS*DHH], g_ks_lo[(size_t)BHH*SS*DHH];
// V transposed, stored as fp16 hi/lo (written by gemm mode 2)
__device__ __half g_vt_hi[(size_t)BHH*DHH*SS], g_vt_lo[(size_t)BHH*DHH*SS]; // [bh][d][s]

// ---------------------------------------------------------------------------
// PTX helpers
// ---------------------------------------------------------------------------
__device__ __forceinline__ uint32_t smem_u32(const void* p) {
    uint32_t a;
    asm("{ .reg .u64 t; cvta.to.shared.u64 t, %1; cvt.u32.u64 %0, t; }" : "=r"(a) : "l"(p));
    return a;
}
__device__ __forceinline__ void cp_async16(uint32_t saddr, const void* gaddr) {
    asm volatile("cp.async.cg.shared.global [%0], [%1], 16;" :: "r"(saddr), "l"(gaddr));
}
__device__ __forceinline__ void cp_commit() { asm volatile("cp.async.commit_group;"); }
template <int N>
__device__ __forceinline__ void cp_wait() { asm volatile("cp.async.wait_group %0;" :: "n"(N)); }

__device__ __forceinline__ void ldm_x4(uint32_t* r, uint32_t addr) {
    asm volatile("ldmatrix.sync.aligned.m8n8.x4.shared.b16 {%0,%1,%2,%3}, [%4];"
        : "=r"(r[0]), "=r"(r[1]), "=r"(r[2]), "=r"(r[3]) : "r"(addr));
}
__device__ __forceinline__ void ldm_x2(uint32_t* r, uint32_t addr) {
    asm volatile("ldmatrix.sync.aligned.m8n8.x2.shared.b16 {%0,%1}, [%2];"
        : "=r"(r[0]), "=r"(r[1]) : "r"(addr));
}
__device__ __forceinline__ void mma_bf16(float* c, const uint32_t* a, const uint32_t* b) {
    asm volatile("mma.sync.aligned.m16n8k16.row.col.f32.bf16.bf16.f32 "
        "{%0,%1,%2,%3}, {%4,%5,%6,%7}, {%8,%9}, {%0,%1,%2,%3};"
        : "+f"(c[0]), "+f"(c[1]), "+f"(c[2]), "+f"(c[3])
        : "r"(a[0]), "r"(a[1]), "r"(a[2]), "r"(a[3]), "r"(b[0]), "r"(b[1]));
}
__device__ __forceinline__ void mma_f16(float* c, const uint32_t* a, const uint32_t* b) {
    asm volatile("mma.sync.aligned.m16n8k16.row.col.f32.f16.f16.f32 "
        "{%0,%1,%2,%3}, {%4,%5,%6,%7}, {%8,%9}, {%0,%1,%2,%3};"
        : "+f"(c[0]), "+f"(c[1]), "+f"(c[2]), "+f"(c[3])
        : "r"(a[0]), "r"(a[1]), "r"(a[2]), "r"(a[3]), "r"(b[0]), "r"(b[1]));
}
// truncation split: hi = top-16 bits (exact), lo = bf16(x - hi); err ~2^-17
__device__ __forceinline__ void split2(float x0, float x1, uint32_t& h, uint32_t& l) {
    uint32_t a = __float_as_uint(x0), b = __float_as_uint(x1);
    h = __byte_perm(a, b, 0x7632);
    float h0 = __uint_as_float(a & 0xFFFF0000u);
    float h1 = __uint_as_float(b & 0xFFFF0000u);
    __nv_bfloat162 ll = __floats2bfloat162_rn(x0 - h0, x1 - h1);
    l = *(uint32_t*)&ll;
}
// fp16 split: hi = f16(x), lo = f16(x - hi)
__device__ __forceinline__ void split2_f16(float x0, float x1, uint32_t& h, uint32_t& l) {
    __half2 hh = __floats2half2_rn(x0, x1);
    float2 f = __half22float2(hh);
    __half2 ll = __floats2half2_rn(x0 - f.x, x1 - f.y);
    h = *(uint32_t*)&hh;
    l = *(uint32_t*)&ll;
}
// exp2 of two fp32 deltas -> fp16x2 probabilities (one MUFU op per pair)
__device__ __forceinline__ uint32_t ex2_f16x2(float lo, float hi) {
    uint32_t t, r;
    asm("cvt.rn.f16x2.f32 %0, %1, %2;" : "=r"(t) : "f"(hi), "f"(lo));
    asm("ex2.approx.f16x2 %0, %1;" : "=r"(r) : "r"(t));
    return r;
}

// ---------------------------------------------------------------------------
// Unified split: y 0..2 inputs (4096 blocks), y 3..6 weights (1024 blocks)
// ---------------------------------------------------------------------------
__global__ __launch_bounds__(256) void split7_kernel(
    const float* __restrict__ x0, const float* __restrict__ x1, const float* __restrict__ x2,
    const float* __restrict__ x3, const float* __restrict__ x4, const float* __restrict__ x5,
    const float* __restrict__ x6,
    __nv_bfloat16* __restrict__ h0d, __nv_bfloat16* __restrict__ h1d, __nv_bfloat16* __restrict__ h2d,
    __nv_bfloat16* __restrict__ h3d, __nv_bfloat16* __restrict__ h4d, __nv_bfloat16* __restrict__ h5d,
    __nv_bfloat16* __restrict__ h6d,
    __nv_bfloat16* __restrict__ l0d, __nv_bfloat16* __restrict__ l1d, __nv_bfloat16* __restrict__ l2d,
    __nv_bfloat16* __restrict__ l3d, __nv_bfloat16* __restrict__ l4d, __nv_bfloat16* __restrict__ l5d,
    __nv_bfloat16* __restrict__ l6d)
{
    const int which = blockIdx.y;
    const int limit = which < 3 ? MM*DD/4 : DD*DD/4;
    int i = blockIdx.x * 256 + threadIdx.x;
    if (i >= limit) return;
    const float* xs[7] = {x0,x1,x2,x3,x4,x5,x6};
    __nv_bfloat16* hs[7] = {h0d,h1d,h2d,h3d,h4d,h5d,h6d};
    __nv_bfloat16* ls[7] = {l0d,l1d,l2d,l3d,l4d,l5d,l6d};
    const float* x = xs[which];
    __nv_bfloat16* hi = hs[which];
    __nv_bfloat16* lo = ls[which];
    float4 f = ((const float4*)x)[i];
    uint32_t ha, hb, la, lb;
    split2(f.x, f.y, ha, la);
    split2(f.z, f.w, hb, lb);
    ((uint32_t*)hi)[2*i] = ha; ((uint32_t*)hi)[2*i+1] = hb;
    ((uint32_t*)lo)[2*i] = la; ((uint32_t*)lo)[2*i+1] = lb;
}

// ---------------------------------------------------------------------------
// Mask dtype detection
// ---------------------------------------------------------------------------
__global__ void detect_mask_kernel(const unsigned int* __restrict__ m) {
    __shared__ int bad;
    if (threadIdx.x == 0) bad = 0;
    __syncthreads();
    int local = 0;
    for (int i = threadIdx.x; i < 8192; i += 256)
        if (m[i] > 1u) local = 1;
    if (local) atomicOr(&bad, 1);
    __syncthreads();
    if (threadIdx.x == 0) g_maskmode = bad ? 0 : 1;
}

// ---------------------------------------------------------------------------
// Batched split-bf16 GEMM, 2-stage cp.async (2 CTAs/SM).
// mode 0: C fp32; mode 1: hi/lo bf16 shaped; mode 2: hi/lo *fp16* Vt [bh][d][s]
// If blockIdx.z == softmax_z: block does a slice of the h0 softmax instead
// (rides along in the same launch, hidden under the GEMM wave).
// ---------------------------------------------------------------------------
#define RS 40
#define TILE_B (128*RS*2)
#define BUF_B  (4*TILE_B)      // 40960
#define GSMEM  (2*BUF_B)       // 81920 -> 2 CTAs/SM

struct ProjArgs {
    const __nv_bfloat16 *Ahi[3], *Alo[3], *Whi[3], *Wlo[3];
    const float* bias[3];
    float* C[3];
    void *Chi[3], *Clo[3];
    float scale[3];
    int mode[3];
    int softmax_z;               // -1 = none
    const float* sm_scores;      // g_attn
    float* sm_out;               // top_attn output
};

__global__ __launch_bounds__(256) void gemm_mma(ProjArgs pa)
{
    extern __shared__ char smem[];
    const int z = blockIdx.z;
    const int tid  = threadIdx.x;

    if (z == pa.softmax_z) {
        // ---- softmax rider: 256 blocks x 16 rows ----
        float* red = (float*)smem;
        const int blk = blockIdx.y * 8 + blockIdx.x;   // 0..255
        for (int rr = 0; rr < 16; rr++) {
            const int r = blk * 16 + rr;               // 0..4095
            const float* row = pa.sm_scores + (size_t)r * SS;
            float vals[8];
            float lmax = -3.4e38f;
#pragma unroll
            for (int i = 0; i < 8; i++) { vals[i] = row[tid + 256*i]; lmax = fmaxf(lmax, vals[i]); }
            red[tid] = lmax; __syncthreads();
            for (int s = 128; s > 0; s >>= 1) { if (tid < s) red[tid] = fmaxf(red[tid], red[tid+s]); __syncthreads(); }
            float m = red[0]; __syncthreads();
            float lsum = 0.f;
#pragma unroll
            for (int i = 0; i < 8; i++) { vals[i] = exp2f(vals[i] - m); lsum += vals[i]; }
            red[tid] = lsum; __syncthreads();
            for (int s = 128; s > 0; s >>= 1) { if (tid < s) red[tid] += red[tid+s]; __syncthreads(); }
            float inv = 1.0f / red[0]; __syncthreads();
            float* tp = pa.sm_out + (size_t)r * SS;
#pragma unroll
            for (int i = 0; i < 8; i++) tp[tid + 256*i] = vals[i] * inv;
        }
        return;
    }

    const int wid  = tid >> 5, lane = tid & 31;
    const int warp_m = wid & 1, warp_n = wid >> 1;
    const int m0 = blockIdx.y * 128, n0 = blockIdx.x * 128;

    const __nv_bfloat16* srcs[4] = {
        pa.Ahi[z] + (size_t)m0 * DD, pa.Alo[z] + (size_t)m0 * DD,
        pa.Whi[z] + (size_t)n0 * DD, pa.Wlo[z] + (size_t)n0 * DD };
    const float* bias = pa.bias[z];
    const float scale = pa.scale[z];
    const int mode = pa.mode[z];

    auto load_chunk = [&](int chunk, int buf) {
        char* sb = smem + buf * BUF_B;
#pragma unroll
        for (int t = 0; t < 4; t++) {
            const __nv_bfloat16* src = srcs[t] + chunk * 32;
            char* dst = sb + t * TILE_B;
#pragma unroll
            for (int it = 0; it < 2; it++) {
                int i = tid + 256 * it;
                int r = i >> 2, seg = i & 3;
                cp_async16(smem_u32(dst + r * (RS*2) + seg * 16),
                           src + (size_t)r * DD + seg * 8);
            }
        }
        cp_commit();
    };

    float acc[4][4][4] = {};

    load_chunk(0, 0);
    for (int chunk = 0; chunk < 32; chunk++) {
        const int buf = chunk & 1;
        if (chunk + 1 < 32) { load_chunk(chunk + 1, buf ^ 1); cp_wait<1>(); }
        else                { cp_wait<0>(); }
        __syncthreads();

        char* sb = smem + buf * BUF_B;
        const uint32_t aHiB = smem_u32(sb);
        const uint32_t aLoB = aHiB + TILE_B;
        const uint32_t bHiB = aHiB + 2*TILE_B;
        const uint32_t bLoB = aHiB + 3*TILE_B;

#pragma unroll
        for (int ks = 0; ks < 2; ks++) {
            const int k0 = ks * 16;
            uint32_t ahi[4][4], alo[4][4], bhi[4][2], blo[4][2];
            {
                const int lr = lane & 15;
                const int ch = (lane >> 4) << 3;
#pragma unroll
                for (int ma = 0; ma < 4; ma++) {
                    uint32_t off = ((warp_m*64 + ma*16 + lr) * RS + k0 + ch) * 2;
                    ldm_x4(ahi[ma], aHiB + off);
                    ldm_x4(alo[ma], aLoB + off);
                }
            }
            {
                const int idx = lane & 15;
                const int nr = idx & 7;
                const int kh = (idx >> 3) << 3;
#pragma unroll
                for (int na = 0; na < 4; na++) {
                    uint32_t off = ((warp_n*32 + na*8 + nr) * RS + k0 + kh) * 2;
                    ldm_x2(bhi[na], bHiB + off);
                    ldm_x2(blo[na], bLoB + off);
                }
            }
#pragma unroll
            for (int ma = 0; ma < 4; ma++)
#pragma unroll
                for (int na = 0; na < 4; na++) {
                    mma_bf16(acc[ma][na], ahi[ma], bhi[na]);
                    mma_bf16(acc[ma][na], ahi[ma], blo[na]);
                    mma_bf16(acc[ma][na], alo[ma], bhi[na]);
                }
        }
        __syncthreads();
    }

    if (mode == 2) {
        float* ts = (float*)smem;                  // [128][133]
#pragma unroll
        for (int ma = 0; ma < 4; ma++) {
            const int rl = warp_m*64 + ma*16 + (lane >> 2);
#pragma unroll
            for (int na = 0; na < 4; na++) {
                const int cl = warp_n*32 + na*8 + (lane & 3)*2;
                const float bx = bias[n0 + cl], by = bias[n0 + cl + 1];
#pragma unroll
                for (int half = 0; half < 2; half++) {
                    ts[(rl + half*8)*133 + cl]     = acc[ma][na][half*2+0] + bx;
                    ts[(rl + half*8)*133 + cl + 1] = acc[ma][na][half*2+1] + by;
                }
            }
        }
        __syncthreads();
        const int b = m0 >> 11, s0 = m0 & (SS-1);
        const int nl = tid >> 1;
        const int soff = (tid & 1) * 64;
        const int n = n0 + nl;
        const int h = n >> 6, dh = n & 63;
        __half* vh = (__half*)pa.Chi[z] + (((size_t)(b*HH + h))*DHH + dh)*SS + s0 + soff;
        __half* vl = (__half*)pa.Clo[z] + (((size_t)(b*HH + h))*DHH + dh)*SS + s0 + soff;
#pragma unroll
        for (int s = 0; s < 64; s += 2) {
            float x0 = ts[(soff + s)*133 + nl];
            float x1 = ts[(soff + s + 1)*133 + nl];
            uint32_t hp, lp;
            split2_f16(x0, x1, hp, lp);
            *(uint32_t*)(vh + s) = hp;
            *(uint32_t*)(vl + s) = lp;
        }
        return;
    }

#pragma unroll
    for (int ma = 0; ma < 4; ma++) {
        const int r0 = m0 + warp_m*64 + ma*16 + (lane >> 2);
#pragma unroll
        for (int na = 0; na < 4; na++) {
            const int c0 = n0 + warp_n*32 + na*8 + (lane & 3)*2;
            const float bx = bias[c0], by = bias[c0+1];
#pragma unroll
            for (int half = 0; half < 2; half++) {
                const int m = r0 + half*8;
                float x0 = (acc[ma][na][half*2+0] + bx) * scale;
                float x1 = (acc[ma][na][half*2+1] + by) * scale;
                if (mode == 1) {
                    int b = m >> 11, s = m & (SS-1);
                    int h = c0 >> 6, dh = c0 & 63;
                    size_t o = (((size_t)b*HH + h)*SS + s)*DHH + dh;
                    uint32_t hp, lp;
                    split2(x0, x1, hp, lp);
                    *(uint32_t*)((__nv_bfloat16*)pa.Chi[z] + o) = hp;
                    *(uint32_t*)((__nv_bfloat16*)pa.Clo[z] + o) = lp;
                } else {
                    *(float2*)&pa.C[z][(size_t)m * DD + c0] = make_float2(x0, x1);
                }
            }
        }
    }
}

// ---------------------------------------------------------------------------
// Fused flash attention (KV chunk 128, 1 CTA/SM).
// P computed in fp16 via ex2.approx.f16x2; PV = 2-term fp16 MMA (Vhi+Vlo fp16).
// h0 CTAs store masked scores to g_attn for top_attn.
// ---------------------------------------------------------------------------
#define RSK 72
#define RSV 136
#define KTILE_B (128*RSK*2)               // 18432
#define VTILE_B (64*RSV*2)                // 17408
#define OFF_K   (2*KTILE_B)
#define OFF_V   (OFF_K + 4*KTILE_B)
#define FSMEM   (OFF_V + 4*VTILE_B)       // 180224

__global__ __launch_bounds__(256, 1) void flash_kernel(
    const __nv_bfloat16* __restrict__ qh, const __nv_bfloat16* __restrict__ ql,
    const __nv_bfloat16* __restrict__ kh, const __nv_bfloat16* __restrict__ kl,
    const __half* __restrict__ vh, const __half* __restrict__ vl,
    const char* __restrict__ mask, float* __restrict__ attn,
    __nv_bfloat16* __restrict__ ctxh, __nv_bfloat16* __restrict__ ctxl)
{
    extern __shared__ char smem[];
    const int tid = threadIdx.x, wid = tid >> 5, lane = tid & 31;
    const int bh = blockIdx.y, q0 = blockIdx.x * 128;
    const int b = bh >> 4, h = bh & 15;
    const int mode = g_maskmode;

    const __nv_bfloat16* qhb = qh + ((size_t)bh*SS + q0) * DHH;
    const __nv_bfloat16* qlb = ql + ((size_t)bh*SS + q0) * DHH;
    const __nv_bfloat16* khb = kh + (size_t)bh*SS*DHH;
    const __nv_bfloat16* klb = kl + (size_t)bh*SS*DHH;
    const __half* vhb = vh + (size_t)bh*DHH*SS;
    const __half* vlb = vl + (size_t)bh*DHH*SS;

    {
        const __nv_bfloat16* s2[2] = { qhb, qlb };
#pragma unroll
        for (int t = 0; t < 2; t++) {
            char* dst = smem + t * KTILE_B;
#pragma unroll
            for (int it = 0; it < 4; it++) {
                int i = tid + it*256;
                int r = i >> 3, seg = i & 7;
                cp_async16(smem_u32(dst + (r*RSK + seg*8)*2), s2[t] + (size_t)r*DHH + seg*8);
            }
        }
        cp_commit();
    }

    auto load_kv = [&](int kt, int buf) {
        char* dk = smem + OFF_K + buf * (2*KTILE_B);
#pragma unroll
        for (int it = 0; it < 4; it++) {
            int i = tid + it*256;
            int r = i >> 3, seg = i & 7;
            cp_async16(smem_u32(dk + (r*RSK + seg*8)*2),
                       khb + ((size_t)(kt*128 + r))*DHH + seg*8);
        }
        dk += KTILE_B;
#pragma unroll
        for (int it = 0; it < 4; it++) {
            int i = tid + it*256;
            int r = i >> 3, seg = i & 7;
            cp_async16(smem_u32(dk + (r*RSK + seg*8)*2),
                       klb + ((size_t)(kt*128 + r))*DHH + seg*8);
        }
        char* dv = smem + OFF_V + buf * (2*VTILE_B);
#pragma unroll
        for (int it = 0; it < 4; it++) {
            int i = tid + it*256;
            int r = i >> 4, seg = i & 15;
            cp_async16(smem_u32(dv + (r*RSV + seg*8)*2),
                       vhb + (size_t)r*SS + kt*128 + seg*8);
        }
        dv += VTILE_B;
#pragma unroll
        for (int it = 0; it < 4; it++) {
            int i = tid + it*256;
            int r = i >> 4, seg = i & 15;
            cp_async16(smem_u32(dv + (r*RSV + seg*8)*2),
                       vlb + (size_t)r*SS + kt*128 + seg*8);
        }
        cp_commit();
    };

    load_kv(0, 0);
    cp_wait<1>();
    __syncthreads();

    uint32_t aqh[4][4], aql[4][4];
    {
        const int lr = lane & 15, ch = (lane >> 4) << 3;
        const uint32_t qHiB = smem_u32(smem), qLoB = qHiB + KTILE_B;
#pragma unroll
        for (int ks = 0; ks < 4; ks++) {
            uint32_t off = ((wid*16 + lr)*RSK + ks*16 + ch)*2;
            ldm_x4(aqh[ks], qHiB + off);
            ldm_x4(aql[ks], qLoB + off);
        }
    }

    const int g = lane >> 2, tg = lane & 3;
    const int r0 = q0 + wid*16 + g;
    const int r1 = r0 + 8;
    const int within = lane & 15;
    const int brow = ((lane >> 4) << 3) + (within & 7);
    const int bcolh = (within >> 3) << 3;

    float m0 = -3.4e38f, m1 = -3.4e38f, l0 = 0.f, l1 = 0.f;
    float acco[8][4] = {};

    for (int kt = 0; kt < 16; kt++) {
        const int buf = kt & 1;
        if (kt < 15) { load_kv(kt + 1, buf ^ 1); cp_wait<1>(); }
        else         { cp_wait<0>(); }
        __syncthreads();

        const uint32_t kHiB = smem_u32(smem + OFF_K + buf*2*KTILE_B);
        const uint32_t kLoB = kHiB + KTILE_B;
        const uint32_t vHiB = smem_u32(smem + OFF_V + buf*2*VTILE_B);
        const uint32_t vLoB = vHiB + VTILE_B;

        // ---- S = Q K^T (3-term bf16) ----
        float accs[16][4];
#pragma unroll
        for (int i = 0; i < 16; i++) { accs[i][0]=0.f; accs[i][1]=0.f; accs[i][2]=0.f; accs[i][3]=0.f; }

#pragma unroll
        for (int np = 0; np < 8; np++) {
#pragma unroll
            for (int ks = 0; ks < 4; ks++) {
                uint32_t bh4[4], bl4[4];
                uint32_t off = ((np*16 + brow)*RSK + ks*16 + bcolh)*2;
                ldm_x4(bh4, kHiB + off);
                ldm_x4(bl4, kLoB + off);
                mma_bf16(accs[2*np],   aqh[ks], bh4);
                mma_bf16(accs[2*np],   aqh[ks], bl4);
                mma_bf16(accs[2*np],   aql[ks], bh4);
                mma_bf16(accs[2*np+1], aqh[ks], bh4+2);
                mma_bf16(accs[2*np+1], aqh[ks], bl4+2);
                mma_bf16(accs[2*np+1], aql[ks], bh4+2);
            }
        }

        // ---- mask select (loads at point of use) ----
        const int kc0 = kt*128 + tg*2;
        if (mode) {
            const int* mb0 = (const int*)mask + ((size_t)b*SS + r0)*SS;
            const int* mb1 = (const int*)mask + ((size_t)b*SS + r1)*SS;
#pragma unroll
            for (int na = 0; na < 16; na++) {
                int c = kc0 + na*8;
                int2 mq0 = *(const int2*)(mb0 + c);
                int2 mq1 = *(const int2*)(mb1 + c);
                if (mq0.x) accs[na][0] = -1e18f;
                if (mq0.y) accs[na][1] = -1e18f;
                if (mq1.x) accs[na][2] = -1e18f;
                if (mq1.y) accs[na][3] = -1e18f;
            }
        } else {
            const unsigned char* mb0 = (const unsigned char*)mask + ((size_t)b*SS + r0)*SS;
            const unsigned char* mb1 = (const unsigned char*)mask + ((size_t)b*SS + r1)*SS;
#pragma unroll
            for (int na = 0; na < 16; na++) {
                int c = kc0 + na*8;
                if (mb0[c])   accs[na][0] = -1e18f;
                if (mb0[c+1]) accs[na][1] = -1e18f;
                if (mb1[c])   accs[na][2] = -1e18f;
                if (mb1[c+1]) accs[na][3] = -1e18f;
            }
        }

        // ---- head-0 score store for top_attn ----
        if (h == 0) {
            float* ar0 = attn + ((size_t)b*SS + r0)*SS;
            float* ar1 = attn + ((size_t)b*SS + r1)*SS;
#pragma unroll
            for (int na = 0; na < 16; na++) {
                int c = kc0 + na*8;
                *(float2*)(ar0 + c) = make_float2(accs[na][0], accs[na][1]);
                *(float2*)(ar1 + c) = make_float2(accs[na][2], accs[na][3]);
            }
        }

        // ---- online softmax: max in fp32, P in fp16 via ex2.approx.f16x2 ----
        float mr0 = -3.4e38f, mr1 = -3.4e38f;
#pragma unroll
        for (int na = 0; na < 16; na++) {
            mr0 = fmaxf(mr0, fmaxf(accs[na][0], accs[na][1]));
            mr1 = fmaxf(mr1, fmaxf(accs[na][2], accs[na][3]));
        }
        mr0 = fmaxf(mr0, __shfl_xor_sync(0xffffffffu, mr0, 1));
        mr0 = fmaxf(mr0, __shfl_xor_sync(0xffffffffu, mr0, 2));
        mr1 = fmaxf(mr1, __shfl_xor_sync(0xffffffffu, mr1, 1));
        mr1 = fmaxf(mr1, __shfl_xor_sync(0xffffffffu, mr1, 2));
        float nm0 = fmaxf(m0, mr0), nm1 = fmaxf(m1, mr1);
        float a0 = exp2f(m0 - nm0), a1 = exp2f(m1 - nm1);
        m0 = nm0; m1 = nm1;

        // P fragments in fp16 (A-fragment layout), plus fp32 row sums
        uint32_t pf[8][4];
        float s0 = 0.f, s1 = 0.f;
#pragma unroll
        for (int j = 0; j < 8; j++) {
#pragma unroll
            for (int pq = 0; pq < 2; pq++) {
                int na = 2*j + pq;
                uint32_t p01 = ex2_f16x2(accs[na][0] - nm0, accs[na][1] - nm0);
                uint32_t p23 = ex2_f16x2(accs[na][2] - nm1, accs[na][3] - nm1);
                pf[j][pq*2+0] = p01;
                pf[j][pq*2+1] = p23;
                float2 f01 = __half22float2(*(__half2*)&p01);
                float2 f23 = __half22float2(*(__half2*)&p23);
                s0 += f01.x + f01.y;
                s1 += f23.x + f23.y;
            }
        }
        s0 += __shfl_xor_sync(0xffffffffu, s0, 1);
        s0 += __shfl_xor_sync(0xffffffffu, s0, 2);
        s1 += __shfl_xor_sync(0xffffffffu, s1, 1);
        s1 += __shfl_xor_sync(0xffffffffu, s1, 2);
        l0 = l0*a0 + s0;
        l1 = l1*a1 + s1;
#pragma unroll
        for (int no = 0; no < 8; no++) {
            acco[no][0] *= a0; acco[no][1] *= a0;
            acco[no][2] *= a1; acco[no][3] *= a1;
        }

        // ---- O += P V (fp16, 2-term: Vhi + Vlo) ----
#pragma unroll
        for (int nop = 0; nop < 4; nop++) {
#pragma unroll
            for (int j = 0; j < 8; j++) {
                uint32_t vb4h[4], vb4l[4];
                uint32_t off = ((nop*16 + brow)*RSV + j*16 + bcolh)*2;
                ldm_x4(vb4h, vHiB + off);
                ldm_x4(vb4l, vLoB + off);
                mma_f16(acco[2*nop],   pf[j], vb4h);
                mma_f16(acco[2*nop],   pf[j], vb4l);
                mma_f16(acco[2*nop+1], pf[j], vb4h+2);
                mma_f16(acco[2*nop+1], pf[j], vb4l+2);
            }
        }
        __syncthreads();
    }

    const float inv0 = 1.f / l0, inv1 = 1.f / l1;
    size_t o0 = ((size_t)(b*SS) + r0)*DD + h*DHH;
    size_t o1 = ((size_t)(b*SS) + r1)*DD + h*DHH;
#pragma unroll
    for (int no = 0; no < 8; no++) {
        int c = no*8 + tg*2;
        uint32_t hp, lp;
        split2(acco[no][0]*inv0, acco[no][1]*inv0, hp, lp);
        *(uint32_t*)(ctxh + o0 + c) = hp;
        *(uint32_t*)(ctxl + o0 + c) = lp;
        split2(acco[no][2]*inv1, acco[no][3]*inv1, hp, lp);
        *(uint32_t*)(ctxh + o1 + c) = hp;
        *(uint32_t*)(ctxl + o1 + c) = lp;
    }
}

// ---------------------------------------------------------------------------
extern "C" void kernel_launch(void* const* d_in, const int* in_sizes, int n_in,
                              void* d_out, int out_size)
{
    const float* key   = (const float*)d_in[0];
    const float* value = (const float*)d_in[1];
    const float* query = (const float*)d_in[2];
    const char*  mask  = (const char*)d_in[3];
    const float* Wk = (const float*)d_in[4];
    const float* bk = (const float*)d_in[5];
    const float* Wv = (const float*)d_in[6];
    const float* bv = (const float*)d_in[7];
    const float* Wq = (const float*)d_in[8];
    const float* bq = (const float*)d_in[9];
    const float* Wo = (const float*)d_in[10];
    const float* bo = (const float*)d_in[11];
    float* out = (float*)d_out;

    float *attn;
    cudaGetSymbolAddress((void**)&attn, g_attn);

    __nv_bfloat16 *keyh,*keyl,*valh,*vall,*qryh,*qryl,*ctxh,*ctxl;
    __nv_bfloat16 *wkh,*wkl,*wvh,*wvl,*wqh,*wql,*woh,*wol;
    __nv_bfloat16 *qsh,*qsl,*ksh,*ksl;
    __half *vth,*vtl;
    cudaGetSymbolAddress((void**)&keyh, g_key_hi); cudaGetSymbolAddress((void**)&keyl, g_key_lo);
    cudaGetSymbolAddress((void**)&valh, g_val_hi); cudaGetSymbolAddress((void**)&vall, g_val_lo);
    cudaGetSymbolAddress((void**)&qryh, g_qry_hi); cudaGetSymbolAddress((void**)&qryl, g_qry_lo);
    cudaGetSymbolAddress((void**)&ctxh, g_ctx_hi); cudaGetSymbolAddress((void**)&ctxl, g_ctx_lo);
    cudaGetSymbolAddress((void**)&wkh,  g_wk_hi);  cudaGetSymbolAddress((void**)&wkl,  g_wk_lo);
    cudaGetSymbolAddress((void**)&wvh,  g_wv_hi);  cudaGetSymbolAddress((void**)&wvl,  g_wv_lo);
    cudaGetSymbolAddress((void**)&wqh,  g_wq_hi);  cudaGetSymbolAddress((void**)&wql,  g_wq_lo);
    cudaGetSymbolAddress((void**)&woh,  g_wo_hi);  cudaGetSymbolAddress((void**)&wol,  g_wo_lo);
    cudaGetSymbolAddress((void**)&qsh,  g_qs_hi);  cudaGetSymbolAddress((void**)&qsl,  g_qs_lo);
    cudaGetSymbolAddress((void**)&ksh,  g_ks_hi);  cudaGetSymbolAddress((void**)&ksl,  g_ks_lo);
    cudaGetSymbolAddress((void**)&vth,  g_vt_hi);  cudaGetSymbolAddress((void**)&vtl,  g_vt_lo);

    cudaFuncSetAttribute(gemm_mma, cudaFuncAttributeMaxDynamicSharedMemorySize, GSMEM);
    cudaFuncSetAttribute(flash_kernel, cudaFuncAttributeMaxDynamicSharedMemorySize, FSMEM);

    detect_mask_kernel<<<1, 256>>>((const unsigned int*)mask);

    // all 7 splits in one launch
    split7_kernel<<<dim3(MM*DD/4/256, 7), 256>>>(
        key, value, query, Wk, Wv, Wq, Wo,
        keyh, valh, qryh, wkh, wvh, wqh, woh,
        keyl, vall, qryl, wkl, wvl, wql, wol);

    ProjArgs pa{};
    pa.Ahi[0]=keyh; pa.Alo[0]=keyl; pa.Whi[0]=wkh; pa.Wlo[0]=wkl; pa.bias[0]=bk;
    pa.Chi[0]=ksh;  pa.Clo[0]=ksl;  pa.scale[0]=1.0f;   pa.mode[0]=1;
    pa.Ahi[1]=valh; pa.Alo[1]=vall; pa.Whi[1]=wvh; pa.Wlo[1]=wvl; pa.bias[1]=bv;
    pa.Chi[1]=vth;  pa.Clo[1]=vtl;  pa.scale[1]=1.0f;   pa.mode[1]=2;
    pa.Ahi[2]=qryh; pa.Alo[2]=qryl; pa.Whi[2]=wqh; pa.Wlo[2]=wql; pa.bias[2]=bq;
    pa.Chi[2]=qsh;  pa.Clo[2]=qsl;  pa.scale[2]=QSCALE; pa.mode[2]=1;
    pa.softmax_z = -1;
    gemm_mma<<<dim3(DD/128, MM/128, 3), 256, GSMEM>>>(pa);

    // fused attention -> ctx hi/lo (+ h0 masked scores into g_attn)
    flash_kernel<<<dim3(SS/128, BHH), 256, FSMEM>>>(qsh, qsl, ksh, ksl, vth, vtl, mask, attn, ctxh, ctxl);

    // output projection + softmax rider (z=1)
    ProjArgs po{};
    po.Ahi[0]=ctxh; po.Alo[0]=ctxl; po.Whi[0]=woh; po.Wlo[0]=wol; po.bias[0]=bo;
    po.C[0]=out; po.scale[0]=1.0f; po.mode[0]=0;
    po.softmax_z = 1;
    po.sm_scores = attn;
    po.sm_out = out + (size_t)MM*DD;
    gemm_mma<<<dim3(DD/128, MM/128, 2), 256, GSMEM>>>(po);
}

// round 15
// speedup vs baseline: 1.6784x; 1.6784x over previous
#include <cuda_runtime.h>
#include <cuda_bf16.h>
#include <cuda_fp16.h>
#include <cstdint>

// Problem constants
#define BB  2
#define SS  2048
#define DD  1024
#define HH  16
#define DHH 64
#define MM  (BB*SS)    // 4096
#define BHH (BB*HH)    // 32

#define QSCALE (0.125f * 1.44269504088896340736f)   // 1/sqrt(64) * log2(e)

// ---------------------------------------------------------------------------
// Scratch (device globals)
// ---------------------------------------------------------------------------
__device__ float g_attn[(size_t)BB*SS*SS];     // head-0 masked scores (32MB)
__device__ int   g_maskmode;

__device__ __nv_bfloat16 g_key_hi[(size_t)MM*DD],  g_key_lo[(size_t)MM*DD];
__device__ __nv_bfloat16 g_val_hi[(size_t)MM*DD],  g_val_lo[(size_t)MM*DD];
__device__ __nv_bfloat16 g_qry_hi[(size_t)MM*DD],  g_qry_lo[(size_t)MM*DD];
__device__ __nv_bfloat16 g_ctx_hi[(size_t)MM*DD],  g_ctx_lo[(size_t)MM*DD];
__device__ __nv_bfloat16 g_wk_hi[(size_t)DD*DD],   g_wk_lo[(size_t)DD*DD];
__device__ __nv_bfloat16 g_wv_hi[(size_t)DD*DD],   g_wv_lo[(size_t)DD*DD];
__device__ __nv_bfloat16 g_wq_hi[(size_t)DD*DD],   g_wq_lo[(size_t)DD*DD];
__device__ __nv_bfloat16 g_wo_hi[(size_t)DD*DD],   g_wo_lo[(size_t)DD*DD];
__device__ __nv_bfloat16 g_qs_hi[(size_t)BHH*SS*DHH], g_qs_lo[(size_t)BHH*SS*DHH];
__device__ __nv_bfloat16 g_ks_hi[(size_t)BHH*SS*DHH], g_ks_lo[(size_t)BHH*SS*DHH];
// V transposed, stored as fp16 hi/lo (written by gemm mode 2)
__device__ __half g_vt_hi[(size_t)BHH*DHH*SS], g_vt_lo[(size_t)BHH*DHH*SS]; // [bh][d][s]

// ---------------------------------------------------------------------------
// PTX helpers
// ---------------------------------------------------------------------------
__device__ __forceinline__ uint32_t smem_u32(const void* p) {
    uint32_t a;
    asm("{ .reg .u64 t; cvta.to.shared.u64 t, %1; cvt.u32.u64 %0, t; }" : "=r"(a) : "l"(p));
    return a;
}
__device__ __forceinline__ void cp_async16(uint32_t saddr, const void* gaddr) {
    asm volatile("cp.async.cg.shared.global [%0], [%1], 16;" :: "r"(saddr), "l"(gaddr));
}
__device__ __forceinline__ void cp_commit() { asm volatile("cp.async.commit_group;"); }
template <int N>
__device__ __forceinline__ void cp_wait() { asm volatile("cp.async.wait_group %0;" :: "n"(N)); }

__device__ __forceinline__ void ldm_x4(uint32_t* r, uint32_t addr) {
    asm volatile("ldmatrix.sync.aligned.m8n8.x4.shared.b16 {%0,%1,%2,%3}, [%4];"
        : "=r"(r[0]), "=r"(r[1]), "=r"(r[2]), "=r"(r[3]) : "r"(addr));
}
__device__ __forceinline__ void ldm_x2(uint32_t* r, uint32_t addr) {
    asm volatile("ldmatrix.sync.aligned.m8n8.x2.shared.b16 {%0,%1}, [%2];"
        : "=r"(r[0]), "=r"(r[1]) : "r"(addr));
}
__device__ __forceinline__ void mma_bf16(float* c, const uint32_t* a, const uint32_t* b) {
    asm volatile("mma.sync.aligned.m16n8k16.row.col.f32.bf16.bf16.f32 "
        "{%0,%1,%2,%3}, {%4,%5,%6,%7}, {%8,%9}, {%0,%1,%2,%3};"
        : "+f"(c[0]), "+f"(c[1]), "+f"(c[2]), "+f"(c[3])
        : "r"(a[0]), "r"(a[1]), "r"(a[2]), "r"(a[3]), "r"(b[0]), "r"(b[1]));
}
__device__ __forceinline__ void mma_f16(float* c, const uint32_t* a, const uint32_t* b) {
    asm volatile("mma.sync.aligned.m16n8k16.row.col.f32.f16.f16.f32 "
        "{%0,%1,%2,%3}, {%4,%5,%6,%7}, {%8,%9}, {%0,%1,%2,%3};"
        : "+f"(c[0]), "+f"(c[1]), "+f"(c[2]), "+f"(c[3])
        : "r"(a[0]), "r"(a[1]), "r"(a[2]), "r"(a[3]), "r"(b[0]), "r"(b[1]));
}
// truncation split: hi = top-16 bits (exact), lo = bf16(x - hi); err ~2^-17
__device__ __forceinline__ void split2(float x0, float x1, uint32_t& h, uint32_t& l) {
    uint32_t a = __float_as_uint(x0), b = __float_as_uint(x1);
    h = __byte_perm(a, b, 0x7632);
    float h0 = __uint_as_float(a & 0xFFFF0000u);
    float h1 = __uint_as_float(b & 0xFFFF0000u);
    __nv_bfloat162 ll = __floats2bfloat162_rn(x0 - h0, x1 - h1);
    l = *(uint32_t*)&ll;
}
// fp16 split: hi = f16(x), lo = f16(x - hi)
__device__ __forceinline__ void split2_f16(float x0, float x1, uint32_t& h, uint32_t& l) {
    __half2 hh = __floats2half2_rn(x0, x1);
    float2 f = __half22float2(hh);
    __half2 ll = __floats2half2_rn(x0 - f.x, x1 - f.y);
    h = *(uint32_t*)&hh;
    l = *(uint32_t*)&ll;
}
// exp2 of two fp32 deltas -> fp16x2 probabilities (one MUFU op per pair)
__device__ __forceinline__ uint32_t ex2_f16x2(float lo, float hi) {
    uint32_t t, r;
    asm("cvt.rn.f16x2.f32 %0, %1, %2;" : "=r"(t) : "f"(hi), "f"(lo));
    asm("ex2.approx.f16x2 %0, %1;" : "=r"(r) : "r"(t));
    return r;
}

// ---------------------------------------------------------------------------
// Batched splits
// ---------------------------------------------------------------------------
__global__ __launch_bounds__(256) void split3_kernel(
    const float* __restrict__ x0, const float* __restrict__ x1, const float* __restrict__ x2,
    __nv_bfloat16* __restrict__ h0d, __nv_bfloat16* __restrict__ h1d, __nv_bfloat16* __restrict__ h2d,
    __nv_bfloat16* __restrict__ l0d, __nv_bfloat16* __restrict__ l1d, __nv_bfloat16* __restrict__ l2d)
{
    const int which = blockIdx.y;
    const float* x = which == 0 ? x0 : which == 1 ? x1 : x2;
    __nv_bfloat16* hi = which == 0 ? h0d : which == 1 ? h1d : h2d;
    __nv_bfloat16* lo = which == 0 ? l0d : which == 1 ? l1d : l2d;
    int i = blockIdx.x * 256 + threadIdx.x;
    float4 f = ((const float4*)x)[i];
    uint32_t ha, hb, la, lb;
    split2(f.x, f.y, ha, la);
    split2(f.z, f.w, hb, lb);
    ((uint32_t*)hi)[2*i] = ha; ((uint32_t*)hi)[2*i+1] = hb;
    ((uint32_t*)lo)[2*i] = la; ((uint32_t*)lo)[2*i+1] = lb;
}
__global__ __launch_bounds__(256) void split4_kernel(
    const float* __restrict__ x0, const float* __restrict__ x1,
    const float* __restrict__ x2, const float* __restrict__ x3,
    __nv_bfloat16* __restrict__ h0d, __nv_bfloat16* __restrict__ h1d,
    __nv_bfloat16* __restrict__ h2d, __nv_bfloat16* __restrict__ h3d,
    __nv_bfloat16* __restrict__ l0d, __nv_bfloat16* __restrict__ l1d,
    __nv_bfloat16* __restrict__ l2d, __nv_bfloat16* __restrict__ l3d)
{
    const int which = blockIdx.y;
    const float* x = which == 0 ? x0 : which == 1 ? x1 : which == 2 ? x2 : x3;
    __nv_bfloat16* hi = which == 0 ? h0d : which == 1 ? h1d : which == 2 ? h2d : h3d;
    __nv_bfloat16* lo = which == 0 ? l0d : which == 1 ? l1d : which == 2 ? l2d : l3d;
    int i = blockIdx.x * 256 + threadIdx.x;
    float4 f = ((const float4*)x)[i];
    uint32_t ha, hb, la, lb;
    split2(f.x, f.y, ha, la);
    split2(f.z, f.w, hb, lb);
    ((uint32_t*)hi)[2*i] = ha; ((uint32_t*)hi)[2*i+1] = hb;
    ((uint32_t*)lo)[2*i] = la; ((uint32_t*)lo)[2*i+1] = lb;
}

// ---------------------------------------------------------------------------
// Mask dtype detection
// ---------------------------------------------------------------------------
__global__ void detect_mask_kernel(const unsigned int* __restrict__ m) {
    __shared__ int bad;
    if (threadIdx.x == 0) bad = 0;
    __syncthreads();
    int local = 0;
    for (int i = threadIdx.x; i < 8192; i += 256)
        if (m[i] > 1u) local = 1;
    if (local) atomicOr(&bad, 1);
    __syncthreads();
    if (threadIdx.x == 0) g_maskmode = bad ? 0 : 1;
}

// ---------------------------------------------------------------------------
// Batched split-bf16 GEMM, 2-stage cp.async (2 CTAs/SM).
// mode 0: C fp32; mode 1: hi/lo bf16 shaped; mode 2: hi/lo *fp16* Vt [bh][d][s]
// ---------------------------------------------------------------------------
#define RS 40
#define TILE_B (128*RS*2)
#define BUF_B  (4*TILE_B)      // 40960
#define GSMEM  (2*BUF_B)       // 81920 -> 2 CTAs/SM

struct ProjArgs {
    const __nv_bfloat16 *Ahi[3], *Alo[3], *Whi[3], *Wlo[3];
    const float* bias[3];
    float* C[3];
    void *Chi[3], *Clo[3];
    float scale[3];
    int mode[3];
};

__global__ __launch_bounds__(256) void gemm_mma(ProjArgs pa)
{
    extern __shared__ char smem[];
    const int z = blockIdx.z;
    const int tid  = threadIdx.x;
    const int wid  = tid >> 5, lane = tid & 31;
    const int warp_m = wid & 1, warp_n = wid >> 1;
    const int m0 = blockIdx.y * 128, n0 = blockIdx.x * 128;

    const __nv_bfloat16* srcs[4] = {
        pa.Ahi[z] + (size_t)m0 * DD, pa.Alo[z] + (size_t)m0 * DD,
        pa.Whi[z] + (size_t)n0 * DD, pa.Wlo[z] + (size_t)n0 * DD };
    const float* bias = pa.bias[z];
    const float scale = pa.scale[z];
    const int mode = pa.mode[z];

    auto load_chunk = [&](int chunk, int buf) {
        char* sb = smem + buf * BUF_B;
#pragma unroll
        for (int t = 0; t < 4; t++) {
            const __nv_bfloat16* src = srcs[t] + chunk * 32;
            char* dst = sb + t * TILE_B;
#pragma unroll
            for (int it = 0; it < 2; it++) {
                int i = tid + 256 * it;
                int r = i >> 2, seg = i & 3;
                cp_async16(smem_u32(dst + r * (RS*2) + seg * 16),
                           src + (size_t)r * DD + seg * 8);
            }
        }
        cp_commit();
    };

    float acc[4][4][4] = {};

    load_chunk(0, 0);
    for (int chunk = 0; chunk < 32; chunk++) {
        const int buf = chunk & 1;
        if (chunk + 1 < 32) { load_chunk(chunk + 1, buf ^ 1); cp_wait<1>(); }
        else                { cp_wait<0>(); }
        __syncthreads();

        char* sb = smem + buf * BUF_B;
        const uint32_t aHiB = smem_u32(sb);
        const uint32_t aLoB = aHiB + TILE_B;
        const uint32_t bHiB = aHiB + 2*TILE_B;
        const uint32_t bLoB = aHiB + 3*TILE_B;

#pragma unroll
        for (int ks = 0; ks < 2; ks++) {
            const int k0 = ks * 16;
            uint32_t ahi[4][4], alo[4][4], bhi[4][2], blo[4][2];
            {
                const int lr = lane & 15;
                const int ch = (lane >> 4) << 3;
#pragma unroll
                for (int ma = 0; ma < 4; ma++) {
                    uint32_t off = ((warp_m*64 + ma*16 + lr) * RS + k0 + ch) * 2;
                    ldm_x4(ahi[ma], aHiB + off);
                    ldm_x4(alo[ma], aLoB + off);
                }
            }
            {
                const int idx = lane & 15;
                const int nr = idx & 7;
                const int kh = (idx >> 3) << 3;
#pragma unroll
                for (int na = 0; na < 4; na++) {
                    uint32_t off = ((warp_n*32 + na*8 + nr) * RS + k0 + kh) * 2;
                    ldm_x2(bhi[na], bHiB + off);
                    ldm_x2(blo[na], bLoB + off);
                }
            }
#pragma unroll
            for (int ma = 0; ma < 4; ma++)
#pragma unroll
                for (int na = 0; na < 4; na++) {
                    mma_bf16(acc[ma][na], ahi[ma], bhi[na]);
                    mma_bf16(acc[ma][na], ahi[ma], blo[na]);
                    mma_bf16(acc[ma][na], alo[ma], bhi[na]);
                }
        }
        __syncthreads();
    }

    if (mode == 2) {
        float* ts = (float*)smem;                  // [128][133]
#pragma unroll
        for (int ma = 0; ma < 4; ma++) {
            const int rl = warp_m*64 + ma*16 + (lane >> 2);
#pragma unroll
            for (int na = 0; na < 4; na++) {
                const int cl = warp_n*32 + na*8 + (lane & 3)*2;
                const float bx = bias[n0 + cl], by = bias[n0 + cl + 1];
#pragma unroll
                for (int half = 0; half < 2; half++) {
                    ts[(rl + half*8)*133 + cl]     = acc[ma][na][half*2+0] + bx;
                    ts[(rl + half*8)*133 + cl + 1] = acc[ma][na][half*2+1] + by;
                }
            }
        }
        __syncthreads();
        const int b = m0 >> 11, s0 = m0 & (SS-1);
        const int nl = tid >> 1;
        const int soff = (tid & 1) * 64;
        const int n = n0 + nl;
        const int h = n >> 6, dh = n & 63;
        __half* vh = (__half*)pa.Chi[z] + (((size_t)(b*HH + h))*DHH + dh)*SS + s0 + soff;
        __half* vl = (__half*)pa.Clo[z] + (((size_t)(b*HH + h))*DHH + dh)*SS + s0 + soff;
#pragma unroll
        for (int s = 0; s < 64; s += 2) {
            float x0 = ts[(soff + s)*133 + nl];
            float x1 = ts[(soff + s + 1)*133 + nl];
            uint32_t hp, lp;
            split2_f16(x0, x1, hp, lp);
            *(uint32_t*)(vh + s) = hp;
            *(uint32_t*)(vl + s) = lp;
        }
        return;
    }

#pragma unroll
    for (int ma = 0; ma < 4; ma++) {
        const int r0 = m0 + warp_m*64 + ma*16 + (lane >> 2);
#pragma unroll
        for (int na = 0; na < 4; na++) {
            const int c0 = n0 + warp_n*32 + na*8 + (lane & 3)*2;
            const float bx = bias[c0], by = bias[c0+1];
#pragma unroll
            for (int half = 0; half < 2; half++) {
                const int m = r0 + half*8;
                float x0 = (acc[ma][na][half*2+0] + bx) * scale;
                float x1 = (acc[ma][na][half*2+1] + by) * scale;
                if (mode == 1) {
                    int b = m >> 11, s = m & (SS-1);
                    int h = c0 >> 6, dh = c0 & 63;
                    size_t o = (((size_t)b*HH + h)*SS + s)*DHH + dh;
                    uint32_t hp, lp;
                    split2(x0, x1, hp, lp);
                    *(uint32_t*)((__nv_bfloat16*)pa.Chi[z] + o) = hp;
                    *(uint32_t*)((__nv_bfloat16*)pa.Clo[z] + o) = lp;
                } else {
                    *(float2*)&pa.C[z][(size_t)m * DD + c0] = make_float2(x0, x1);
                }
            }
        }
    }
}

// ---------------------------------------------------------------------------
// Fused flash attention (KV chunk 128, 1 CTA/SM).
// P computed in fp16 via ex2.approx.f16x2; PV = 2-term fp16 MMA (Vhi+Vlo fp16).
// h0 CTAs store masked scores to g_attn for top_attn.
// ---------------------------------------------------------------------------
#define RSK 72
#define RSV 136
#define KTILE_B (128*RSK*2)               // 18432
#define VTILE_B (64*RSV*2)                // 17408
#define OFF_K   (2*KTILE_B)
#define OFF_V   (OFF_K + 4*KTILE_B)
#define FSMEM   (OFF_V + 4*VTILE_B)       // 180224

__global__ __launch_bounds__(256, 1) void flash_kernel(
    const __nv_bfloat16* __restrict__ qh, const __nv_bfloat16* __restrict__ ql,
    const __nv_bfloat16* __restrict__ kh, const __nv_bfloat16* __restrict__ kl,
    const __half* __restrict__ vh, const __half* __restrict__ vl,
    const char* __restrict__ mask, float* __restrict__ attn,
    __nv_bfloat16* __restrict__ ctxh, __nv_bfloat16* __restrict__ ctxl)
{
    extern __shared__ char smem[];
    const int tid = threadIdx.x, wid = tid >> 5, lane = tid & 31;
    const int bh = blockIdx.y, q0 = blockIdx.x * 128;
    const int b = bh >> 4, h = bh & 15;
    const int mode = g_maskmode;

    const __nv_bfloat16* qhb = qh + ((size_t)bh*SS + q0) * DHH;
    const __nv_bfloat16* qlb = ql + ((size_t)bh*SS + q0) * DHH;
    const __nv_bfloat16* khb = kh + (size_t)bh*SS*DHH;
    const __nv_bfloat16* klb = kl + (size_t)bh*SS*DHH;
    const __half* vhb = vh + (size_t)bh*DHH*SS;
    const __half* vlb = vl + (size_t)bh*DHH*SS;

    {
        const __nv_bfloat16* s2[2] = { qhb, qlb };
#pragma unroll
        for (int t = 0; t < 2; t++) {
            char* dst = smem + t * KTILE_B;
#pragma unroll
            for (int it = 0; it < 4; it++) {
                int i = tid + it*256;
                int r = i >> 3, seg = i & 7;
                cp_async16(smem_u32(dst + (r*RSK + seg*8)*2), s2[t] + (size_t)r*DHH + seg*8);
            }
        }
        cp_commit();
    }

    auto load_kv = [&](int kt, int buf) {
        char* dk = smem + OFF_K + buf * (2*KTILE_B);
#pragma unroll
        for (int it = 0; it < 4; it++) {
            int i = tid + it*256;
            int r = i >> 3, seg = i & 7;
            cp_async16(smem_u32(dk + (r*RSK + seg*8)*2),
                       khb + ((size_t)(kt*128 + r))*DHH + seg*8);
        }
        dk += KTILE_B;
#pragma unroll
        for (int it = 0; it < 4; it++) {
            int i = tid + it*256;
            int r = i >> 3, seg = i & 7;
            cp_async16(smem_u32(dk + (r*RSK + seg*8)*2),
                       klb + ((size_t)(kt*128 + r))*DHH + seg*8);
        }
        char* dv = smem + OFF_V + buf * (2*VTILE_B);
#pragma unroll
        for (int it = 0; it < 4; it++) {
            int i = tid + it*256;
            int r = i >> 4, seg = i & 15;
            cp_async16(smem_u32(dv + (r*RSV + seg*8)*2),
                       vhb + (size_t)r*SS + kt*128 + seg*8);
        }
        dv += VTILE_B;
#pragma unroll
        for (int it = 0; it < 4; it++) {
            int i = tid + it*256;
            int r = i >> 4, seg = i & 15;
            cp_async16(smem_u32(dv + (r*RSV + seg*8)*2),
                       vlb + (size_t)r*SS + kt*128 + seg*8);
        }
        cp_commit();
    };

    load_kv(0, 0);
    cp_wait<1>();
    __syncthreads();

    uint32_t aqh[4][4], aql[4][4];
    {
        const int lr = lane & 15, ch = (lane >> 4) << 3;
        const uint32_t qHiB = smem_u32(smem), qLoB = qHiB + KTILE_B;
#pragma unroll
        for (int ks = 0; ks < 4; ks++) {
            uint32_t off = ((wid*16 + lr)*RSK + ks*16 + ch)*2;
            ldm_x4(aqh[ks], qHiB + off);
            ldm_x4(aql[ks], qLoB + off);
        }
    }

    const int g = lane >> 2, tg = lane & 3;
    const int r0 = q0 + wid*16 + g;
    const int r1 = r0 + 8;
    const int within = lane & 15;
    const int brow = ((lane >> 4) << 3) + (within & 7);
    const int bcolh = (within >> 3) << 3;

    float m0 = -3.4e38f, m1 = -3.4e38f, l0 = 0.f, l1 = 0.f;
    float acco[8][4] = {};

    for (int kt = 0; kt < 16; kt++) {
        const int buf = kt & 1;
        if (kt < 15) { load_kv(kt + 1, buf ^ 1); cp_wait<1>(); }
        else         { cp_wait<0>(); }
        __syncthreads();

        const uint32_t kHiB = smem_u32(smem + OFF_K + buf*2*KTILE_B);
        const uint32_t kLoB = kHiB + KTILE_B;
        const uint32_t vHiB = smem_u32(smem + OFF_V + buf*2*VTILE_B);
        const uint32_t vLoB = vHiB + VTILE_B;

        // ---- S = Q K^T (3-term bf16) ----
        float accs[16][4];
#pragma unroll
        for (int i = 0; i < 16; i++) { accs[i][0]=0.f; accs[i][1]=0.f; accs[i][2]=0.f; accs[i][3]=0.f; }

#pragma unroll
        for (int np = 0; np < 8; np++) {
#pragma unroll
            for (int ks = 0; ks < 4; ks++) {
                uint32_t bh4[4], bl4[4];
                uint32_t off = ((np*16 + brow)*RSK + ks*16 + bcolh)*2;
                ldm_x4(bh4, kHiB + off);
                ldm_x4(bl4, kLoB + off);
                mma_bf16(accs[2*np],   aqh[ks], bh4);
                mma_bf16(accs[2*np],   aqh[ks], bl4);
                mma_bf16(accs[2*np],   aql[ks], bh4);
                mma_bf16(accs[2*np+1], aqh[ks], bh4+2);
                mma_bf16(accs[2*np+1], aqh[ks], bl4+2);
                mma_bf16(accs[2*np+1], aql[ks], bh4+2);
            }
        }

        // ---- mask select (loads at point of use) ----
        const int kc0 = kt*128 + tg*2;
        if (mode) {
            const int* mb0 = (const int*)mask + ((size_t)b*SS + r0)*SS;
            const int* mb1 = (const int*)mask + ((size_t)b*SS + r1)*SS;
#pragma unroll
            for (int na = 0; na < 16; na++) {
                int c = kc0 + na*8;
                int2 mq0 = *(const int2*)(mb0 + c);
                int2 mq1 = *(const int2*)(mb1 + c);
                if (mq0.x) accs[na][0] = -1e18f;
                if (mq0.y) accs[na][1] = -1e18f;
                if (mq1.x) accs[na][2] = -1e18f;
                if (mq1.y) accs[na][3] = -1e18f;
            }
        } else {
            const unsigned char* mb0 = (const unsigned char*)mask + ((size_t)b*SS + r0)*SS;
            const unsigned char* mb1 = (const unsigned char*)mask + ((size_t)b*SS + r1)*SS;
#pragma unroll
            for (int na = 0; na < 16; na++) {
                int c = kc0 + na*8;
                if (mb0[c])   accs[na][0] = -1e18f;
                if (mb0[c+1]) accs[na][1] = -1e18f;
                if (mb1[c])   accs[na][2] = -1e18f;
                if (mb1[c+1]) accs[na][3] = -1e18f;
            }
        }

        // ---- head-0 score store for top_attn ----
        if (h == 0) {
            float* ar0 = attn + ((size_t)b*SS + r0)*SS;
            float* ar1 = attn + ((size_t)b*SS + r1)*SS;
#pragma unroll
            for (int na = 0; na < 16; na++) {
                int c = kc0 + na*8;
                *(float2*)(ar0 + c) = make_float2(accs[na][0], accs[na][1]);
                *(float2*)(ar1 + c) = make_float2(accs[na][2], accs[na][3]);
            }
        }

        // ---- online softmax: max in fp32, P in fp16 via ex2.approx.f16x2 ----
        float mr0 = -3.4e38f, mr1 = -3.4e38f;
#pragma unroll
        for (int na = 0; na < 16; na++) {
            mr0 = fmaxf(mr0, fmaxf(accs[na][0], accs[na][1]));
            mr1 = fmaxf(mr1, fmaxf(accs[na][2], accs[na][3]));
        }
        mr0 = fmaxf(mr0, __shfl_xor_sync(0xffffffffu, mr0, 1));
        mr0 = fmaxf(mr0, __shfl_xor_sync(0xffffffffu, mr0, 2));
        mr1 = fmaxf(mr1, __shfl_xor_sync(0xffffffffu, mr1, 1));
        mr1 = fmaxf(mr1, __shfl_xor_sync(0xffffffffu, mr1, 2));
        float nm0 = fmaxf(m0, mr0), nm1 = fmaxf(m1, mr1);
        float a0 = exp2f(m0 - nm0), a1 = exp2f(m1 - nm1);
        m0 = nm0; m1 = nm1;

        // P fragments in fp16 (A-fragment layout), plus fp32 row sums
        uint32_t pf[8][4];
        float s0 = 0.f, s1 = 0.f;
#pragma unroll
        for (int j = 0; j < 8; j++) {
#pragma unroll
            for (int pq = 0; pq < 2; pq++) {
                int na = 2*j + pq;
                uint32_t p01 = ex2_f16x2(accs[na][0] - nm0, accs[na][1] - nm0);
                uint32_t p23 = ex2_f16x2(accs[na][2] - nm1, accs[na][3] - nm1);
                pf[j][pq*2+0] = p01;
                pf[j][pq*2+1] = p23;
                float2 f01 = __half22float2(*(__half2*)&p01);
                float2 f23 = __half22float2(*(__half2*)&p23);
                s0 += f01.x + f01.y;
                s1 += f23.x + f23.y;
            }
        }
        s0 += __shfl_xor_sync(0xffffffffu, s0, 1);
        s0 += __shfl_xor_sync(0xffffffffu, s0, 2);
        s1 += __shfl_xor_sync(0xffffffffu, s1, 1);
        s1 += __shfl_xor_sync(0xffffffffu, s1, 2);
        l0 = l0*a0 + s0;
        l1 = l1*a1 + s1;
#pragma unroll
        for (int no = 0; no < 8; no++) {
            acco[no][0] *= a0; acco[no][1] *= a0;
            acco[no][2] *= a1; acco[no][3] *= a1;
        }

        // ---- O += P V (fp16, 2-term: Vhi + Vlo) ----
#pragma unroll
        for (int nop = 0; nop < 4; nop++) {
#pragma unroll
            for (int j = 0; j < 8; j++) {
                uint32_t vb4h[4], vb4l[4];
                uint32_t off = ((nop*16 + brow)*RSV + j*16 + bcolh)*2;
                ldm_x4(vb4h, vHiB + off);
                ldm_x4(vb4l, vLoB + off);
                mma_f16(acco[2*nop],   pf[j], vb4h);
                mma_f16(acco[2*nop],   pf[j], vb4l);
                mma_f16(acco[2*nop+1], pf[j], vb4h+2);
                mma_f16(acco[2*nop+1], pf[j], vb4l+2);
            }
        }
        __syncthreads();
    }

    const float inv0 = 1.f / l0, inv1 = 1.f / l1;
    size_t o0 = ((size_t)(b*SS) + r0)*DD + h*DHH;
    size_t o1 = ((size_t)(b*SS) + r1)*DD + h*DHH;
#pragma unroll
    for (int no = 0; no < 8; no++) {
        int c = no*8 + tg*2;
        uint32_t hp, lp;
        split2(acco[no][0]*inv0, acco[no][1]*inv0, hp, lp);
        *(uint32_t*)(ctxh + o0 + c) = hp;
        *(uint32_t*)(ctxl + o0 + c) = lp;
        split2(acco[no][2]*inv1, acco[no][3]*inv1, hp, lp);
        *(uint32_t*)(ctxh + o1 + c) = hp;
        *(uint32_t*)(ctxl + o1 + c) = lp;
    }
}

// ---------------------------------------------------------------------------
// head-0 softmax (exp2, logits pre-scaled) -> top_attn output
// ---------------------------------------------------------------------------
__global__ __launch_bounds__(256) void softmax_h0_kernel(
    const float* __restrict__ scores, float* __restrict__ topattn)
{
    const int r = blockIdx.x;
    const float* row = scores + (size_t)r * SS;
    const int tid = threadIdx.x;
    __shared__ float red[256];

    float vals[8];
    float lmax = -3.4e38f;
#pragma unroll
    for (int i=0;i<8;i++) { vals[i] = row[tid + 256*i]; lmax = fmaxf(lmax, vals[i]); }
    red[tid] = lmax; __syncthreads();
    for (int s=128; s>0; s>>=1) { if (tid < s) red[tid] = fmaxf(red[tid], red[tid+s]); __syncthreads(); }
    float m = red[0]; __syncthreads();

    float lsum = 0.f;
#pragma unroll
    for (int i=0;i<8;i++) { vals[i] = exp2f(vals[i] - m); lsum += vals[i]; }
    red[tid] = lsum; __syncthreads();
    for (int s=128; s>0; s>>=1) { if (tid < s) red[tid] += red[tid+s]; __syncthreads(); }
    float inv = 1.0f / red[0];

    float* tp = topattn + (size_t)r * SS;
#pragma unroll
    for (int i=0;i<8;i++) tp[tid + 256*i] = vals[i] * inv;
}

// ---------------------------------------------------------------------------
extern "C" void kernel_launch(void* const* d_in, const int* in_sizes, int n_in,
                              void* d_out, int out_size)
{
    const float* key   = (const float*)d_in[0];
    const float* value = (const float*)d_in[1];
    const float* query = (const float*)d_in[2];
    const char*  mask  = (const char*)d_in[3];
    const float* Wk = (const float*)d_in[4];
    const float* bk = (const float*)d_in[5];
    const float* Wv = (const float*)d_in[6];
    const float* bv = (const float*)d_in[7];
    const float* Wq = (const float*)d_in[8];
    const float* bq = (const float*)d_in[9];
    const float* Wo = (const float*)d_in[10];
    const float* bo = (const float*)d_in[11];
    float* out = (float*)d_out;

    float *attn;
    cudaGetSymbolAddress((void**)&attn, g_attn);

    __nv_bfloat16 *keyh,*keyl,*valh,*vall,*qryh,*qryl,*ctxh,*ctxl;
    __nv_bfloat16 *wkh,*wkl,*wvh,*wvl,*wqh,*wql,*woh,*wol;
    __nv_bfloat16 *qsh,*qsl,*ksh,*ksl;
    __half *vth,*vtl;
    cudaGetSymbolAddress((void**)&keyh, g_key_hi); cudaGetSymbolAddress((void**)&keyl, g_key_lo);
    cudaGetSymbolAddress((void**)&valh, g_val_hi); cudaGetSymbolAddress((void**)&vall, g_val_lo);
    cudaGetSymbolAddress((void**)&qryh, g_qry_hi); cudaGetSymbolAddress((void**)&qryl, g_qry_lo);
    cudaGetSymbolAddress((void**)&ctxh, g_ctx_hi); cudaGetSymbolAddress((void**)&ctxl, g_ctx_lo);
    cudaGetSymbolAddress((void**)&wkh,  g_wk_hi);  cudaGetSymbolAddress((void**)&wkl,  g_wk_lo);
    cudaGetSymbolAddress((void**)&wvh,  g_wv_hi);  cudaGetSymbolAddress((void**)&wvl,  g_wv_lo);
    cudaGetSymbolAddress((void**)&wqh,  g_wq_hi);  cudaGetSymbolAddress((void**)&wql,  g_wq_lo);
    cudaGetSymbolAddress((void**)&woh,  g_wo_hi);  cudaGetSymbolAddress((void**)&wol,  g_wo_lo);
    cudaGetSymbolAddress((void**)&qsh,  g_qs_hi);  cudaGetSymbolAddress((void**)&qsl,  g_qs_lo);
    cudaGetSymbolAddress((void**)&ksh,  g_ks_hi);  cudaGetSymbolAddress((void**)&ksl,  g_ks_lo);
    cudaGetSymbolAddress((void**)&vth,  g_vt_hi);  cudaGetSymbolAddress((void**)&vtl,  g_vt_lo);

    cudaFuncSetAttribute(gemm_mma, cudaFuncAttributeMaxDynamicSharedMemorySize, GSMEM);
    cudaFuncSetAttribute(flash_kernel, cudaFuncAttributeMaxDynamicSharedMemorySize, FSMEM);

    detect_mask_kernel<<<1, 256>>>((const unsigned int*)mask);

    split3_kernel<<<dim3(MM*DD/4/256, 3), 256>>>(key, value, query,
        keyh, valh, qryh, keyl, vall, qryl);
    split4_kernel<<<dim3(DD*DD/4/256, 4), 256>>>(Wk, Wv, Wq, Wo,
        wkh, wvh, wqh, woh, wkl, wvl, wql, wol);

    ProjArgs pa{};
    pa.Ahi[0]=keyh; pa.Alo[0]=keyl; pa.Whi[0]=wkh; pa.Wlo[0]=wkl; pa.bias[0]=bk;
    pa.Chi[0]=ksh;  pa.Clo[0]=ksl;  pa.scale[0]=1.0f;   pa.mode[0]=1;
    pa.Ahi[1]=valh; pa.Alo[1]=vall; pa.Whi[1]=wvh; pa.Wlo[1]=wvl; pa.bias[1]=bv;
    pa.Chi[1]=vth;  pa.Clo[1]=vtl;  pa.scale[1]=1.0f;   pa.mode[1]=2;
    pa.Ahi[2]=qryh; pa.Alo[2]=qryl; pa.Whi[2]=wqh; pa.Wlo[2]=wql; pa.bias[2]=bq;
    pa.Chi[2]=qsh;  pa.Clo[2]=qsl;  pa.scale[2]=QSCALE; pa.mode[2]=1;
    gemm_mma<<<dim3(DD/128, MM/128, 3), 256, GSMEM>>>(pa);

    // fused attention -> ctx hi/lo (+ h0 masked scores into g_attn)
    flash_kernel<<<dim3(SS/128, BHH), 256, FSMEM>>>(qsh, qsl, ksh, ksl, vth, vtl, mask, attn, ctxh, ctxl);

    // top_attn from flash-stored h0 scores
    softmax_h0_kernel<<<BB*SS, 256>>>(attn, out + (size_t)MM*DD);

    // output projection
    ProjArgs po{};
    po.Ahi[0]=ctxh; po.Alo[0]=ctxl; po.Whi[0]=woh; po.Wlo[0]=wol; po.bias[0]=bo;
    po.C[0]=out; po.scale[0]=1.0f; po.mode[0]=0;
    gemm_mma<<<dim3(DD/128, MM/128, 1), 256, GSMEM>>>(po);
}

// round 17
// speedup vs baseline: 1.7412x; 1.0374x over previous
#include <cuda_runtime.h>
#include <cuda_bf16.h>
#include <cuda_fp16.h>
#include <cstdint>

// Problem constants
#define BB  2
#define SS  2048
#define DD  1024
#define HH  16
#define DHH 64
#define MM  (BB*SS)    // 4096
#define BHH (BB*HH)    // 32

#define QSCALE (0.125f * 1.44269504088896340736f)   // 1/sqrt(64) * log2(e)

// ---------------------------------------------------------------------------
// Scratch (device globals)
// ---------------------------------------------------------------------------
__device__ float g_attn[(size_t)BB*SS*SS];     // head-0 masked scores (32MB)
__device__ int   g_maskmode;

__device__ __nv_bfloat16 g_key_hi[(size_t)MM*DD],  g_key_lo[(size_t)MM*DD];
__device__ __nv_bfloat16 g_val_hi[(size_t)MM*DD],  g_val_lo[(size_t)MM*DD];
__device__ __nv_bfloat16 g_qry_hi[(size_t)MM*DD],  g_qry_lo[(size_t)MM*DD];
__device__ __nv_bfloat16 g_ctx_hi[(size_t)MM*DD],  g_ctx_lo[(size_t)MM*DD];
__device__ __nv_bfloat16 g_wk_hi[(size_t)DD*DD],   g_wk_lo[(size_t)DD*DD];
__device__ __nv_bfloat16 g_wv_hi[(size_t)DD*DD],   g_wv_lo[(size_t)DD*DD];
__device__ __nv_bfloat16 g_wq_hi[(size_t)DD*DD],   g_wq_lo[(size_t)DD*DD];
__device__ __nv_bfloat16 g_wo_hi[(size_t)DD*DD],   g_wo_lo[(size_t)DD*DD];
__device__ __nv_bfloat16 g_qs_hi[(size_t)BHH*SS*DHH], g_qs_lo[(size_t)BHH*SS*DHH];
__device__ __nv_bfloat16 g_ks_hi[(size_t)BHH*SS*DHH], g_ks_lo[(size_t)BHH*SS*DHH];
// V transposed, stored as fp16 hi/lo (written by gemm mode 2)
__device__ __half g_vt_hi[(size_t)BHH*DHH*SS], g_vt_lo[(size_t)BHH*DHH*SS]; // [bh][d][s]

// ---------------------------------------------------------------------------
// PTX helpers
// ---------------------------------------------------------------------------
__device__ __forceinline__ uint32_t smem_u32(const void* p) {
    uint32_t a;
    asm("{ .reg .u64 t; cvta.to.shared.u64 t, %1; cvt.u32.u64 %0, t; }" : "=r"(a) : "l"(p));
    return a;
}
__device__ __forceinline__ void cp_async16(uint32_t saddr, const void* gaddr) {
    asm volatile("cp.async.cg.shared.global [%0], [%1], 16;" :: "r"(saddr), "l"(gaddr));
}
__device__ __forceinline__ void cp_commit() { asm volatile("cp.async.commit_group;"); }
template <int N>
__device__ __forceinline__ void cp_wait() { asm volatile("cp.async.wait_group %0;" :: "n"(N)); }

__device__ __forceinline__ void ldm_x4(uint32_t* r, uint32_t addr) {
    asm volatile("ldmatrix.sync.aligned.m8n8.x4.shared.b16 {%0,%1,%2,%3}, [%4];"
        : "=r"(r[0]), "=r"(r[1]), "=r"(r[2]), "=r"(r[3]) : "r"(addr));
}
__device__ __forceinline__ void ldm_x2(uint32_t* r, uint32_t addr) {
    asm volatile("ldmatrix.sync.aligned.m8n8.x2.shared.b16 {%0,%1}, [%2];"
        : "=r"(r[0]), "=r"(r[1]) : "r"(addr));
}
__device__ __forceinline__ void mma_bf16(float* c, const uint32_t* a, const uint32_t* b) {
    asm volatile("mma.sync.aligned.m16n8k16.row.col.f32.bf16.bf16.f32 "
        "{%0,%1,%2,%3}, {%4,%5,%6,%7}, {%8,%9}, {%0,%1,%2,%3};"
        : "+f"(c[0]), "+f"(c[1]), "+f"(c[2]), "+f"(c[3])
        : "r"(a[0]), "r"(a[1]), "r"(a[2]), "r"(a[3]), "r"(b[0]), "r"(b[1]));
}
__device__ __forceinline__ void mma_f16(float* c, const uint32_t* a, const uint32_t* b) {
    asm volatile("mma.sync.aligned.m16n8k16.row.col.f32.f16.f16.f32 "
        "{%0,%1,%2,%3}, {%4,%5,%6,%7}, {%8,%9}, {%0,%1,%2,%3};"
        : "+f"(c[0]), "+f"(c[1]), "+f"(c[2]), "+f"(c[3])
        : "r"(a[0]), "r"(a[1]), "r"(a[2]), "r"(a[3]), "r"(b[0]), "r"(b[1]));
}
// truncation split: hi = top-16 bits (exact), lo = bf16(x - hi); err ~2^-17
__device__ __forceinline__ void split2(float x0, float x1, uint32_t& h, uint32_t& l) {
    uint32_t a = __float_as_uint(x0), b = __float_as_uint(x1);
    h = __byte_perm(a, b, 0x7632);
    float h0 = __uint_as_float(a & 0xFFFF0000u);
    float h1 = __uint_as_float(b & 0xFFFF0000u);
    __nv_bfloat162 ll = __floats2bfloat162_rn(x0 - h0, x1 - h1);
    l = *(uint32_t*)&ll;
}
// fp16 split: hi = f16(x), lo = f16(x - hi)
__device__ __forceinline__ void split2_f16(float x0, float x1, uint32_t& h, uint32_t& l) {
    __half2 hh = __floats2half2_rn(x0, x1);
    float2 f = __half22float2(hh);
    __half2 ll = __floats2half2_rn(x0 - f.x, x1 - f.y);
    h = *(uint32_t*)&hh;
    l = *(uint32_t*)&ll;
}
// exp2 of two fp32 deltas -> fp16x2 probabilities (one MUFU op per pair)
__device__ __forceinline__ uint32_t ex2_f16x2(float lo, float hi) {
    uint32_t t, r;
    asm("cvt.rn.f16x2.f32 %0, %1, %2;" : "=r"(t) : "f"(hi), "f"(lo));
    asm("ex2.approx.f16x2 %0, %1;" : "=r"(r) : "r"(t));
    return r;
}

// ---------------------------------------------------------------------------
// Batched splits
// ---------------------------------------------------------------------------
__global__ __launch_bounds__(256) void split3_kernel(
    const float* __restrict__ x0, const float* __restrict__ x1, const float* __restrict__ x2,
    __nv_bfloat16* __restrict__ h0d, __nv_bfloat16* __restrict__ h1d, __nv_bfloat16* __restrict__ h2d,
    __nv_bfloat16* __restrict__ l0d, __nv_bfloat16* __restrict__ l1d, __nv_bfloat16* __restrict__ l2d)
{
    const int which = blockIdx.y;
    const float* x = which == 0 ? x0 : which == 1 ? x1 : x2;
    __nv_bfloat16* hi = which == 0 ? h0d : which == 1 ? h1d : h2d;
    __nv_bfloat16* lo = which == 0 ? l0d : which == 1 ? l1d : l2d;
    int i = blockIdx.x * 256 + threadIdx.x;
    float4 f = ((const float4*)x)[i];
    uint32_t ha, hb, la, lb;
    split2(f.x, f.y, ha, la);
    split2(f.z, f.w, hb, lb);
    ((uint32_t*)hi)[2*i] = ha; ((uint32_t*)hi)[2*i+1] = hb;
    ((uint32_t*)lo)[2*i] = la; ((uint32_t*)lo)[2*i+1] = lb;
}
__global__ __launch_bounds__(256) void split4_kernel(
    const float* __restrict__ x0, const float* __restrict__ x1,
    const float* __restrict__ x2, const float* __restrict__ x3,
    __nv_bfloat16* __restrict__ h0d, __nv_bfloat16* __restrict__ h1d,
    __nv_bfloat16* __restrict__ h2d, __nv_bfloat16* __restrict__ h3d,
    __nv_bfloat16* __restrict__ l0d, __nv_bfloat16* __restrict__ l1d,
    __nv_bfloat16* __restrict__ l2d, __nv_bfloat16* __restrict__ l3d)
{
    const int which = blockIdx.y;
    const float* x = which == 0 ? x0 : which == 1 ? x1 : which == 2 ? x2 : x3;
    __nv_bfloat16* hi = which == 0 ? h0d : which == 1 ? h1d : which == 2 ? h2d : h3d;
    __nv_bfloat16* lo = which == 0 ? l0d : which == 1 ? l1d : which == 2 ? l2d : l3d;
    int i = blockIdx.x * 256 + threadIdx.x;
    float4 f = ((const float4*)x)[i];
    uint32_t ha, hb, la, lb;
    split2(f.x, f.y, ha, la);
    split2(f.z, f.w, hb, lb);
    ((uint32_t*)hi)[2*i] = ha; ((uint32_t*)hi)[2*i+1] = hb;
    ((uint32_t*)lo)[2*i] = la; ((uint32_t*)lo)[2*i+1] = lb;
}

// ---------------------------------------------------------------------------
// Mask dtype detection
// ---------------------------------------------------------------------------
__global__ void detect_mask_kernel(const unsigned int* __restrict__ m) {
    __shared__ int bad;
    if (threadIdx.x == 0) bad = 0;
    __syncthreads();
    int local = 0;
    for (int i = threadIdx.x; i < 8192; i += 256)
        if (m[i] > 1u) local = 1;
    if (local) atomicOr(&bad, 1);
    __syncthreads();
    if (threadIdx.x == 0) g_maskmode = bad ? 0 : 1;
}

// ---------------------------------------------------------------------------
// Batched split-bf16 GEMM, 2-stage cp.async (2 CTAs/SM).
// Single sync per chunk: cp_wait -> sync -> issue next load -> compute.
// mode 0: C fp32; mode 1: hi/lo bf16 shaped; mode 2: hi/lo *fp16* Vt [bh][d][s]
// ---------------------------------------------------------------------------
#define RS 40
#define TILE_B (128*RS*2)
#define BUF_B  (4*TILE_B)      // 40960
#define GSMEM  (2*BUF_B)       // 81920 -> 2 CTAs/SM

struct ProjArgs {
    const __nv_bfloat16 *Ahi[3], *Alo[3], *Whi[3], *Wlo[3];
    const float* bias[3];
    float* C[3];
    void *Chi[3], *Clo[3];
    float scale[3];
    int mode[3];
};

__global__ __launch_bounds__(256) void gemm_mma(ProjArgs pa)
{
    extern __shared__ char smem[];
    const int z = blockIdx.z;
    const int tid  = threadIdx.x;
    const int wid  = tid >> 5, lane = tid & 31;
    const int warp_m = wid & 1, warp_n = wid >> 1;
    const int m0 = blockIdx.y * 128, n0 = blockIdx.x * 128;

    const __nv_bfloat16* srcs[4] = {
        pa.Ahi[z] + (size_t)m0 * DD, pa.Alo[z] + (size_t)m0 * DD,
        pa.Whi[z] + (size_t)n0 * DD, pa.Wlo[z] + (size_t)n0 * DD };
    const float* bias = pa.bias[z];
    const float scale = pa.scale[z];
    const int mode = pa.mode[z];

    auto load_chunk = [&](int chunk, int buf) {
        char* sb = smem + buf * BUF_B;
#pragma unroll
        for (int t = 0; t < 4; t++) {
            const __nv_bfloat16* src = srcs[t] + chunk * 32;
            char* dst = sb + t * TILE_B;
#pragma unroll
            for (int it = 0; it < 2; it++) {
                int i = tid + 256 * it;
                int r = i >> 2, seg = i & 3;
                cp_async16(smem_u32(dst + r * (RS*2) + seg * 16),
                           src + (size_t)r * DD + seg * 8);
            }
        }
        cp_commit();
    };

    float acc[4][4][4] = {};

    load_chunk(0, 0);
    for (int chunk = 0; chunk < 32; chunk++) {
        const int buf = chunk & 1;
        cp_wait<0>();      // this thread's group for chunk complete
        __syncthreads();   // all threads' waits done (visibility) + buf^1 free
        if (chunk + 1 < 32) load_chunk(chunk + 1, buf ^ 1);

        char* sb = smem + buf * BUF_B;
        const uint32_t aHiB = smem_u32(sb);
        const uint32_t aLoB = aHiB + TILE_B;
        const uint32_t bHiB = aHiB + 2*TILE_B;
        const uint32_t bLoB = aHiB + 3*TILE_B;

#pragma unroll
        for (int ks = 0; ks < 2; ks++) {
            const int k0 = ks * 16;
            uint32_t ahi[4][4], alo[4][4], bhi[4][2], blo[4][2];
            {
                const int lr = lane & 15;
                const int ch = (lane >> 4) << 3;
#pragma unroll
                for (int ma = 0; ma < 4; ma++) {
                    uint32_t off = ((warp_m*64 + ma*16 + lr) * RS + k0 + ch) * 2;
                    ldm_x4(ahi[ma], aHiB + off);
                    ldm_x4(alo[ma], aLoB + off);
                }
            }
            {
                const int idx = lane & 15;
                const int nr = idx & 7;
                const int kh = (idx >> 3) << 3;
#pragma unroll
                for (int na = 0; na < 4; na++) {
                    uint32_t off = ((warp_n*32 + na*8 + nr) * RS + k0 + kh) * 2;
                    ldm_x2(bhi[na], bHiB + off);
                    ldm_x2(blo[na], bLoB + off);
                }
            }
#pragma unroll
            for (int ma = 0; ma < 4; ma++)
#pragma unroll
                for (int na = 0; na < 4; na++) {
                    mma_bf16(acc[ma][na], ahi[ma], bhi[na]);
                    mma_bf16(acc[ma][na], ahi[ma], blo[na]);
                    mma_bf16(acc[ma][na], alo[ma], bhi[na]);
                }
        }
    }

    if (mode == 2) {
        __syncthreads();   // all warps done with smem tiles before staging reuse
        float* ts = (float*)smem;                  // [128][133]
#pragma unroll
        for (int ma = 0; ma < 4; ma++) {
            const int rl = warp_m*64 + ma*16 + (lane >> 2);
#pragma unroll
            for (int na = 0; na < 4; na++) {
                const int cl = warp_n*32 + na*8 + (lane & 3)*2;
                const float bx = bias[n0 + cl], by = bias[n0 + cl + 1];
#pragma unroll
                for (int half = 0; half < 2; half++) {
                    ts[(rl + half*8)*133 + cl]     = acc[ma][na][half*2+0] + bx;
                    ts[(rl + half*8)*133 + cl + 1] = acc[ma][na][half*2+1] + by;
                }
            }
        }
        __syncthreads();
        const int b = m0 >> 11, s0 = m0 & (SS-1);
        const int nl = tid >> 1;
        const int soff = (tid & 1) * 64;
        const int n = n0 + nl;
        const int h = n >> 6, dh = n & 63;
        __half* vh = (__half*)pa.Chi[z] + (((size_t)(b*HH + h))*DHH + dh)*SS + s0 + soff;
        __half* vl = (__half*)pa.Clo[z] + (((size_t)(b*HH + h))*DHH + dh)*SS + s0 + soff;
#pragma unroll
        for (int s = 0; s < 64; s += 2) {
            float x0 = ts[(soff + s)*133 + nl];
            float x1 = ts[(soff + s + 1)*133 + nl];
            uint32_t hp, lp;
            split2_f16(x0, x1, hp, lp);
            *(uint32_t*)(vh + s) = hp;
            *(uint32_t*)(vl + s) = lp;
        }
        return;
    }

#pragma unroll
    for (int ma = 0; ma < 4; ma++) {
        const int r0 = m0 + warp_m*64 + ma*16 + (lane >> 2);
#pragma unroll
        for (int na = 0; na < 4; na++) {
            const int c0 = n0 + warp_n*32 + na*8 + (lane & 3)*2;
            const float bx = bias[c0], by = bias[c0+1];
#pragma unroll
            for (int half = 0; half < 2; half++) {
                const int m = r0 + half*8;
                float x0 = (acc[ma][na][half*2+0] + bx) * scale;
                float x1 = (acc[ma][na][half*2+1] + by) * scale;
                if (mode == 1) {
                    int b = m >> 11, s = m & (SS-1);
                    int h = c0 >> 6, dh = c0 & 63;
                    size_t o = (((size_t)b*HH + h)*SS + s)*DHH + dh;
                    uint32_t hp, lp;
                    split2(x0, x1, hp, lp);
                    *(uint32_t*)((__nv_bfloat16*)pa.Chi[z] + o) = hp;
                    *(uint32_t*)((__nv_bfloat16*)pa.Clo[z] + o) = lp;
                } else {
                    *(float2*)&pa.C[z][(size_t)m * DD + c0] = make_float2(x0, x1);
                }
            }
        }
    }
}

// ---------------------------------------------------------------------------
// Fused flash attention (KV chunk 128, 1 CTA/SM).
// Single sync per chunk: cp_wait -> sync -> issue next load -> compute.
// P computed in fp16 via ex2.approx.f16x2; PV = 2-term fp16 MMA (Vhi+Vlo fp16).
// h0 CTAs store masked scores to g_attn for top_attn.
// ---------------------------------------------------------------------------
#define RSK 72
#define RSV 136
#define KTILE_B (128*RSK*2)               // 18432
#define VTILE_B (64*RSV*2)                // 17408
#define OFF_K   (2*KTILE_B)
#define OFF_V   (OFF_K + 4*KTILE_B)
#define FSMEM   (OFF_V + 4*VTILE_B)       // 180224

__global__ __launch_bounds__(256, 1) void flash_kernel(
    const __nv_bfloat16* __restrict__ qh, const __nv_bfloat16* __restrict__ ql,
    const __nv_bfloat16* __restrict__ kh, const __nv_bfloat16* __restrict__ kl,
    const __half* __restrict__ vh, const __half* __restrict__ vl,
    const char* __restrict__ mask, float* __restrict__ attn,
    __nv_bfloat16* __restrict__ ctxh, __nv_bfloat16* __restrict__ ctxl)
{
    extern __shared__ char smem[];
    const int tid = threadIdx.x, wid = tid >> 5, lane = tid & 31;
    const int bh = blockIdx.y, q0 = blockIdx.x * 128;
    const int b = bh >> 4, h = bh & 15;
    const int mode = g_maskmode;

    const __nv_bfloat16* qhb = qh + ((size_t)bh*SS + q0) * DHH;
    const __nv_bfloat16* qlb = ql + ((size_t)bh*SS + q0) * DHH;
    const __nv_bfloat16* khb = kh + (size_t)bh*SS*DHH;
    const __nv_bfloat16* klb = kl + (size_t)bh*SS*DHH;
    const __half* vhb = vh + (size_t)bh*DHH*SS;
    const __half* vlb = vl + (size_t)bh*DHH*SS;

    {
        const __nv_bfloat16* s2[2] = { qhb, qlb };
#pragma unroll
        for (int t = 0; t < 2; t++) {
            char* dst = smem + t * KTILE_B;
#pragma unroll
            for (int it = 0; it < 4; it++) {
                int i = tid + it*256;
                int r = i >> 3, seg = i & 7;
                cp_async16(smem_u32(dst + (r*RSK + seg*8)*2), s2[t] + (size_t)r*DHH + seg*8);
            }
        }
        cp_commit();
    }

    auto load_kv = [&](int kt, int buf) {
        char* dk = smem + OFF_K + buf * (2*KTILE_B);
#pragma unroll
        for (int it = 0; it < 4; it++) {
            int i = tid + it*256;
            int r = i >> 3, seg = i & 7;
            cp_async16(smem_u32(dk + (r*RSK + seg*8)*2),
                       khb + ((size_t)(kt*128 + r))*DHH + seg*8);
        }
        dk += KTILE_B;
#pragma unroll
        for (int it = 0; it < 4; it++) {
            int i = tid + it*256;
            int r = i >> 3, seg = i & 7;
            cp_async16(smem_u32(dk + (r*RSK + seg*8)*2),
                       klb + ((size_t)(kt*128 + r))*DHH + seg*8);
        }
        char* dv = smem + OFF_V + buf * (2*VTILE_B);
#pragma unroll
        for (int it = 0; it < 4; it++) {
            int i = tid + it*256;
            int r = i >> 4, seg = i & 15;
            cp_async16(smem_u32(dv + (r*RSV + seg*8)*2),
                       vhb + (size_t)r*SS + kt*128 + seg*8);
        }
        dv += VTILE_B;
#pragma unroll
        for (int it = 0; it < 4; it++) {
            int i = tid + it*256;
            int r = i >> 4, seg = i & 15;
            cp_async16(smem_u32(dv + (r*RSV + seg*8)*2),
                       vlb + (size_t)r*SS + kt*128 + seg*8);
        }
        cp_commit();
    };

    load_kv(0, 0);
    cp_wait<0>();      // Q tile + kv0 both resident for this thread
    __syncthreads();   // visibility across warps

    uint32_t aqh[4][4], aql[4][4];
    {
        const int lr = lane & 15, ch = (lane >> 4) << 3;
        const uint32_t qHiB = smem_u32(smem), qLoB = qHiB + KTILE_B;
#pragma unroll
        for (int ks = 0; ks < 4; ks++) {
            uint32_t off = ((wid*16 + lr)*RSK + ks*16 + ch)*2;
            ldm_x4(aqh[ks], qHiB + off);
            ldm_x4(aql[ks], qLoB + off);
        }
    }

    const int g = lane >> 2, tg = lane & 3;
    const int r0 = q0 + wid*16 + g;
    const int r1 = r0 + 8;
    const int within = lane & 15;
    const int brow = ((lane >> 4) << 3) + (within & 7);
    const int bcolh = (within >> 3) << 3;

    float m0 = -3.4e38f, m1 = -3.4e38f, l0 = 0.f, l1 = 0.f;
    float acco[8][4] = {};

    for (int kt = 0; kt < 16; kt++) {
        const int buf = kt & 1;
        if (kt > 0) {
            cp_wait<0>();      // chunk kt complete for this thread
            __syncthreads();   // visibility + buf^1 free (compute kt-1 done)
        }
        if (kt < 15) load_kv(kt + 1, buf ^ 1);

        const uint32_t kHiB = smem_u32(smem + OFF_K + buf*2*KTILE_B);
        const uint32_t kLoB = kHiB + KTILE_B;
        const uint32_t vHiB = smem_u32(smem + OFF_V + buf*2*VTILE_B);
        const uint32_t vLoB = vHiB + VTILE_B;

        // ---- S = Q K^T (3-term bf16) ----
        float accs[16][4];
#pragma unroll
        for (int i = 0; i < 16; i++) { accs[i][0]=0.f; accs[i][1]=0.f; accs[i][2]=0.f; accs[i][3]=0.f; }

#pragma unroll
        for (int np = 0; np < 8; np++) {
#pragma unroll
            for (int ks = 0; ks < 4; ks++) {
                uint32_t bh4[4], bl4[4];
                uint32_t off = ((np*16 + brow)*RSK + ks*16 + bcolh)*2;
                ldm_x4(bh4, kHiB + off);
                ldm_x4(bl4, kLoB + off);
                mma_bf16(accs[2*np],   aqh[ks], bh4);
                mma_bf16(accs[2*np],   aqh[ks], bl4);
                mma_bf16(accs[2*np],   aql[ks], bh4);
                mma_bf16(accs[2*np+1], aqh[ks], bh4+2);
                mma_bf16(accs[2*np+1], aqh[ks], bl4+2);
                mma_bf16(accs[2*np+1], aql[ks], bh4+2);
            }
        }

        // ---- mask select (loads at point of use) ----
        const int kc0 = kt*128 + tg*2;
        if (mode) {
            const int* mb0 = (const int*)mask + ((size_t)b*SS + r0)*SS;
            const int* mb1 = (const int*)mask + ((size_t)b*SS + r1)*SS;
#pragma unroll
            for (int na = 0; na < 16; na++) {
                int c = kc0 + na*8;
                int2 mq0 = *(const int2*)(mb0 + c);
                int2 mq1 = *(const int2*)(mb1 + c);
                if (mq0.x) accs[na][0] = -1e18f;
                if (mq0.y) accs[na][1] = -1e18f;
                if (mq1.x) accs[na][2] = -1e18f;
                if (mq1.y) accs[na][3] = -1e18f;
            }
        } else {
            const unsigned char* mb0 = (const unsigned char*)mask + ((size_t)b*SS + r0)*SS;
            const unsigned char* mb1 = (const unsigned char*)mask + ((size_t)b*SS + r1)*SS;
#pragma unroll
            for (int na = 0; na < 16; na++) {
                int c = kc0 + na*8;
                if (mb0[c])   accs[na][0] = -1e18f;
                if (mb0[c+1]) accs[na][1] = -1e18f;
                if (mb1[c])   accs[na][2] = -1e18f;
                if (mb1[c+1]) accs[na][3] = -1e18f;
            }
        }

        // ---- head-0 score store for top_attn ----
        if (h == 0) {
            float* ar0 = attn + ((size_t)b*SS + r0)*SS;
            float* ar1 = attn + ((size_t)b*SS + r1)*SS;
#pragma unroll
            for (int na = 0; na < 16; na++) {
                int c = kc0 + na*8;
                *(float2*)(ar0 + c) = make_float2(accs[na][0], accs[na][1]);
                *(float2*)(ar1 + c) = make_float2(accs[na][2], accs[na][3]);
            }
        }

        // ---- online softmax: max in fp32, P in fp16 via ex2.approx.f16x2 ----
        float mr0 = -3.4e38f, mr1 = -3.4e38f;
#pragma unroll
        for (int na = 0; na < 16; na++) {
            mr0 = fmaxf(mr0, fmaxf(accs[na][0], accs[na][1]));
            mr1 = fmaxf(mr1, fmaxf(accs[na][2], accs[na][3]));
        }
        mr0 = fmaxf(mr0, __shfl_xor_sync(0xffffffffu, mr0, 1));
        mr0 = fmaxf(mr0, __shfl_xor_sync(0xffffffffu, mr0, 2));
        mr1 = fmaxf(mr1, __shfl_xor_sync(0xffffffffu, mr1, 1));
        mr1 = fmaxf(mr1, __shfl_xor_sync(0xffffffffu, mr1, 2));
        float nm0 = fmaxf(m0, mr0), nm1 = fmaxf(m1, mr1);
        float a0 = exp2f(m0 - nm0), a1 = exp2f(m1 - nm1);
        m0 = nm0; m1 = nm1;

        // P fragments in fp16 (A-fragment layout), plus fp32 row sums
        uint32_t pf[8][4];
        float s0 = 0.f, s1 = 0.f;
#pragma unroll
        for (int j = 0; j < 8; j++) {
#pragma unroll
            for (int pq = 0; pq < 2; pq++) {
                int na = 2*j + pq;
                uint32_t p01 = ex2_f16x2(accs[na][0] - nm0, accs[na][1] - nm0);
                uint32_t p23 = ex2_f16x2(accs[na][2] - nm1, accs[na][3] - nm1);
                pf[j][pq*2+0] = p01;
                pf[j][pq*2+1] = p23;
                float2 f01 = __half22float2(*(__half2*)&p01);
                float2 f23 = __half22float2(*(__half2*)&p23);
                s0 += f01.x + f01.y;
                s1 += f23.x + f23.y;
            }
        }
        s0 += __shfl_xor_sync(0xffffffffu, s0, 1);
        s0 += __shfl_xor_sync(0xffffffffu, s0, 2);
        s1 += __shfl_xor_sync(0xffffffffu, s1, 1);
        s1 += __shfl_xor_sync(0xffffffffu, s1, 2);
        l0 = l0*a0 + s0;
        l1 = l1*a1 + s1;
#pragma unroll
        for (int no = 0; no < 8; no++) {
            acco[no][0] *= a0; acco[no][1] *= a0;
            acco[no][2] *= a1; acco[no][3] *= a1;
        }

        // ---- O += P V (fp16, 2-term: Vhi + Vlo) ----
#pragma unroll
        for (int nop = 0; nop < 4; nop++) {
#pragma unroll
            for (int j = 0; j < 8; j++) {
                uint32_t vb4h[4], vb4l[4];
                uint32_t off = ((nop*16 + brow)*RSV + j*16 + bcolh)*2;
                ldm_x4(vb4h, vHiB + off);
                ldm_x4(vb4l, vLoB + off);
                mma_f16(acco[2*nop],   pf[j], vb4h);
                mma_f16(acco[2*nop],   pf[j], vb4l);
                mma_f16(acco[2*nop+1], pf[j], vb4h+2);
                mma_f16(acco[2*nop+1], pf[j], vb4l+2);
            }
        }
    }

    const float inv0 = 1.f / l0, inv1 = 1.f / l1;
    size_t o0 = ((size_t)(b*SS) + r0)*DD + h*DHH;
    size_t o1 = ((size_t)(b*SS) + r1)*DD + h*DHH;
#pragma unroll
    for (int no = 0; no < 8; no++) {
        int c = no*8 + tg*2;
        uint32_t hp, lp;
        split2(acco[no][0]*inv0, acco[no][1]*inv0, hp, lp);
        *(uint32_t*)(ctxh + o0 + c) = hp;
        *(uint32_t*)(ctxl + o0 + c) = lp;
        split2(acco[no][2]*inv1, acco[no][3]*inv1, hp, lp);
        *(uint32_t*)(ctxh + o1 + c) = hp;
        *(uint32_t*)(ctxl + o1 + c) = lp;
    }
}

// ---------------------------------------------------------------------------
// head-0 softmax (exp2, logits pre-scaled) -> top_attn output
// ---------------------------------------------------------------------------
__global__ __launch_bounds__(256) void softmax_h0_kernel(
    const float* __restrict__ scores, float* __restrict__ topattn)
{
    const int r = blockIdx.x;
    const float* row = scores + (size_t)r * SS;
    const int tid = threadIdx.x;
    __shared__ float red[256];

    float vals[8];
    float lmax = -3.4e38f;
#pragma unroll
    for (int i=0;i<8;i++) { vals[i] = row[tid + 256*i]; lmax = fmaxf(lmax, vals[i]); }
    red[tid] = lmax; __syncthreads();
    for (int s=128; s>0; s>>=1) { if (tid < s) red[tid] = fmaxf(red[tid], red[tid+s]); __syncthreads(); }
    float m = red[0]; __syncthreads();

    float lsum = 0.f;
#pragma unroll
    for (int i=0;i<8;i++) { vals[i] = exp2f(vals[i] - m); lsum += vals[i]; }
    red[tid] = lsum; __syncthreads();
    for (int s=128; s>0; s>>=1) { if (tid < s) red[tid] += red[tid+s]; __syncthreads(); }
    float inv = 1.0f / red[0];

    float* tp = topattn + (size_t)r * SS;
#pragma unroll
    for (int i=0;i<8;i++) tp[tid + 256*i] = vals[i] * inv;
}

// ---------------------------------------------------------------------------
extern "C" void kernel_launch(void* const* d_in, const int* in_sizes, int n_in,
                              void* d_out, int out_size)
{
    const float* key   = (const float*)d_in[0];
    const float* value = (const float*)d_in[1];
    const float* query = (const float*)d_in[2];
    const char*  mask  = (const char*)d_in[3];
    const float* Wk = (const float*)d_in[4];
    const float* bk = (const float*)d_in[5];
    const float* Wv = (const float*)d_in[6];
    const float* bv = (const float*)d_in[7];
    const float* Wq = (const float*)d_in[8];
    const float* bq = (const float*)d_in[9];
    const float* Wo = (const float*)d_in[10];
    const float* bo = (const float*)d_in[11];
    float* out = (float*)d_out;

    float *attn;
    cudaGetSymbolAddress((void**)&attn, g_attn);

    __nv_bfloat16 *keyh,*keyl,*valh,*vall,*qryh,*qryl,*ctxh,*ctxl;
    __nv_bfloat16 *wkh,*wkl,*wvh,*wvl,*wqh,*wql,*woh,*wol;
    __nv_bfloat16 *qsh,*qsl,*ksh,*ksl;
    __half *vth,*vtl;
    cudaGetSymbolAddress((void**)&keyh, g_key_hi); cudaGetSymbolAddress((void**)&keyl, g_key_lo);
    cudaGetSymbolAddress((void**)&valh, g_val_hi); cudaGetSymbolAddress((void**)&vall, g_val_lo);
    cudaGetSymbolAddress((void**)&qryh, g_qry_hi); cudaGetSymbolAddress((void**)&qryl, g_qry_lo);
    cudaGetSymbolAddress((void**)&ctxh, g_ctx_hi); cudaGetSymbolAddress((void**)&ctxl, g_ctx_lo);
    cudaGetSymbolAddress((void**)&wkh,  g_wk_hi);  cudaGetSymbolAddress((void**)&wkl,  g_wk_lo);
    cudaGetSymbolAddress((void**)&wvh,  g_wv_hi);  cudaGetSymbolAddress((void**)&wvl,  g_wv_lo);
    cudaGetSymbolAddress((void**)&wqh,  g_wq_hi);  cudaGetSymbolAddress((void**)&wql,  g_wq_lo);
    cudaGetSymbolAddress((void**)&woh,  g_wo_hi);  cudaGetSymbolAddress((void**)&wol,  g_wo_lo);
    cudaGetSymbolAddress((void**)&qsh,  g_qs_hi);  cudaGetSymbolAddress((void**)&qsl,  g_qs_lo);
    cudaGetSymbolAddress((void**)&ksh,  g_ks_hi);  cudaGetSymbolAddress((void**)&ksl,  g_ks_lo);
    cudaGetSymbolAddress((void**)&vth,  g_vt_hi);  cudaGetSymbolAddress((void**)&vtl,  g_vt_lo);

    cudaFuncSetAttribute(gemm_mma, cudaFuncAttributeMaxDynamicSharedMemorySize, GSMEM);
    cudaFuncSetAttribute(flash_kernel, cudaFuncAttributeMaxDynamicSharedMemorySize, FSMEM);

    detect_mask_kernel<<<1, 256>>>((const unsigned int*)mask);

    split3_kernel<<<dim3(MM*DD/4/256, 3), 256>>>(key, value, query,
        keyh, valh, qryh, keyl, vall, qryl);
    split4_kernel<<<dim3(DD*DD/4/256, 4), 256>>>(Wk, Wv, Wq, Wo,
        wkh, wvh, wqh, woh, wkl, wvl, wql, wol);

    ProjArgs pa{};
    pa.Ahi[0]=keyh; pa.Alo[0]=keyl; pa.Whi[0]=wkh; pa.Wlo[0]=wkl; pa.bias[0]=bk;
    pa.Chi[0]=ksh;  pa.Clo[0]=ksl;  pa.scale[0]=1.0f;   pa.mode[0]=1;
    pa.Ahi[1]=valh; pa.Alo[1]=vall; pa.Whi[1]=wvh; pa.Wlo[1]=wvl; pa.bias[1]=bv;
    pa.Chi[1]=vth;  pa.Clo[1]=vtl;  pa.scale[1]=1.0f;   pa.mode[1]=2;
    pa.Ahi[2]=qryh; pa.Alo[2]=qryl; pa.Whi[2]=wqh; pa.Wlo[2]=wql; pa.bias[2]=bq;
    pa.Chi[2]=qsh;  pa.Clo[2]=qsl;  pa.scale[2]=QSCALE; pa.mode[2]=1;
    gemm_mma<<<dim3(DD/128, MM/128, 3), 256, GSMEM>>>(pa);

    // fused attention -> ctx hi/lo (+ h0 masked scores into g_attn)
    flash_kernel<<<dim3(SS/128, BHH), 256, FSMEM>>>(qsh, qsl, ksh, ksl, vth, vtl, mask, attn, ctxh, ctxl);

    // top_attn from flash-stored h0 scores
    softmax_h0_kernel<<<BB*SS, 256>>>(attn, out + (size_t)MM*DD);

    // output projection
    ProjArgs po{};
    po.Ahi[0]=ctxh; po.Alo[0]=ctxl; po.Whi[0]=woh; po.Wlo[0]=wol; po.bias[0]=bo;
    po.C[0]=out; po.scale[0]=1.0f; po.mode[0]=0;
    gemm_mma<<<dim3(DD/128, MM/128, 1), 256, GSMEM>>>(po);
}